// round 6
// baseline (speedup 1.0000x reference)
#include <cuda_runtime.h>

// Problem shapes (fixed for this instance)
#define BS 8
#define NH 8
#define SL 512
#define HD 64
#define NP 1024

#define TI 16     // query rows per CTA
#define NT 256    // threads per CTA
#define CHUNK 128 // staging chunk (rows of K/V/r_k/r_v)

// SMEM layout (floats), odd strides to dodge bank conflicts
#define SQ_STRIDE 65
#define SA_STRIDE 1025
#define BUF_STRIDE 65
#define SS_STRIDE 513

#define SQ_OFF 0
#define SA_OFF (TI * SQ_STRIDE)                    // 1040
#define BUF_OFF (SA_OFF + TI * SA_STRIDE)          // 17440
#define SS_OFF (BUF_OFF + CHUNK * BUF_STRIDE)      // 25760
#define SMEM_FLOATS (SS_OFF + TI * SS_STRIDE)      // 33968
#define SMEM_BYTES (SMEM_FLOATS * 4)               // 135872 bytes

#define ATTN_ELEMS ((size_t)BS * NH * SL * HD)     // 2,097,152
#define P_ELEMS ((size_t)BS * NH * SL * SL)        // 16,777,216
#define R_ELEMS ((size_t)BS * NH * NP * HD)        // 4,194,304

// Fallback scratch if the harness only wants p_attn (defensive)
__device__ float g_attn_scratch[ATTN_ELEMS];
// path_map dtype flag: 1 if the buffer is int64 (odd int32 words all zero), else 0
__device__ int g_pm_is64;

// ---- detect whether path_map is int64 or int32 ----
// If int64 with values in [0,1024], every odd int32 word is 0.
// For genuine int32 data (uniform in [0,1024]), 4096 samples all being zero
// has probability ~(1/1025)^4096 ~= 0.
__global__ void detect_pm_kernel(const int* __restrict__ pm32)
{
    __shared__ int any_nonzero;
    if (threadIdx.x == 0) any_nonzero = 0;
    __syncthreads();
    for (int i = threadIdx.x; i < 4096; i += blockDim.x) {
        if (pm32[2 * i + 1] != 0) any_nonzero = 1;
    }
    __syncthreads();
    if (threadIdx.x == 0) g_pm_is64 = (any_nonzero == 0) ? 1 : 0;
}

__global__ void __launch_bounds__(NT, 1)
rel_attn_kernel(const float* __restrict__ Q, const float* __restrict__ K,
                const float* __restrict__ V, const float* __restrict__ RK,
                const float* __restrict__ RV, const int* __restrict__ PM32,
                const int* __restrict__ MSK,
                float* __restrict__ out_attn, float* __restrict__ out_p)
{
    extern __shared__ float sm[];
    float* sQ   = sm + SQ_OFF;   // [TI][65]
    float* sSA  = sm + SA_OFF;   // [TI][1025]  (col NP == zero row; later reused as scatter buf)
    float* sBuf = sm + BUF_OFF;  // [128][65]
    float* sS   = sm + SS_OFF;   // [TI][513]

    const int b = blockIdx.z, h = blockIdx.y;
    const int i0 = blockIdx.x * TI;
    const int tid = threadIdx.x;
    const int pmshift = g_pm_is64;   // 0: int32 layout, 1: int64 layout (low word)

    const size_t bh = (size_t)b * NH + h;
    const size_t qbase  = (bh * SL + i0) * HD;
    const size_t kvbase = bh * SL * HD;
    const size_t rbase  = bh * NP * HD;

    // ---- load Q tile ----
    for (int t = tid; t < TI * HD; t += NT) {
        int r = t >> 6, k = t & 63;
        sQ[r * SQ_STRIDE + k] = Q[qbase + (size_t)r * HD + k];
    }
    if (tid < TI) sSA[tid * SA_STRIDE + NP] = 0.f;  // zero-row for idx==P
    __syncthreads();

    // dot-phase thread tile: 2 rows x 4 cols within each 128-col chunk
    const int r2 = (tid & 7) * 2;
    const int c4 = (tid >> 3) * 4;

    // ==== SA[16][1024] = Qtile @ RK^T ====
    for (int p0 = 0; p0 < NP; p0 += CHUNK) {
        for (int t = tid; t < CHUNK * HD; t += NT) {
            int p = t >> 6, k = t & 63;
            sBuf[p * BUF_STRIDE + k] = RK[rbase + (size_t)(p0 + p) * HD + k];
        }
        __syncthreads();
        float acc[2][4] = {};
        const float* q0 = sQ + r2 * SQ_STRIDE;
        const float* q1 = sQ + (r2 + 1) * SQ_STRIDE;
        const float* w0 = sBuf + (c4 + 0) * BUF_STRIDE;
        const float* w1 = sBuf + (c4 + 1) * BUF_STRIDE;
        const float* w2 = sBuf + (c4 + 2) * BUF_STRIDE;
        const float* w3 = sBuf + (c4 + 3) * BUF_STRIDE;
        #pragma unroll 16
        for (int k = 0; k < HD; k++) {
            float a0 = q0[k], a1 = q1[k];
            float x0 = w0[k], x1 = w1[k], x2 = w2[k], x3 = w3[k];
            acc[0][0] += a0 * x0; acc[0][1] += a0 * x1; acc[0][2] += a0 * x2; acc[0][3] += a0 * x3;
            acc[1][0] += a1 * x0; acc[1][1] += a1 * x1; acc[1][2] += a1 * x2; acc[1][3] += a1 * x3;
        }
        #pragma unroll
        for (int n = 0; n < 4; n++) {
            sSA[r2 * SA_STRIDE + p0 + c4 + n]       = acc[0][n];
            sSA[(r2 + 1) * SA_STRIDE + p0 + c4 + n] = acc[1][n];
        }
        __syncthreads();
    }

    // ==== S[16][512] = Qtile @ K^T + gather(SA, path_map), scale, mask ====
    const float inv = 0.125f;  // 1/sqrt(64)
    for (int j0 = 0; j0 < SL; j0 += CHUNK) {
        for (int t = tid; t < CHUNK * HD; t += NT) {
            int j = t >> 6, k = t & 63;
            sBuf[j * BUF_STRIDE + k] = K[kvbase + (size_t)(j0 + j) * HD + k];
        }
        __syncthreads();
        float acc[2][4] = {};
        const float* q0 = sQ + r2 * SQ_STRIDE;
        const float* q1 = sQ + (r2 + 1) * SQ_STRIDE;
        const float* w0 = sBuf + (c4 + 0) * BUF_STRIDE;
        const float* w1 = sBuf + (c4 + 1) * BUF_STRIDE;
        const float* w2 = sBuf + (c4 + 2) * BUF_STRIDE;
        const float* w3 = sBuf + (c4 + 3) * BUF_STRIDE;
        #pragma unroll 16
        for (int k = 0; k < HD; k++) {
            float a0 = q0[k], a1 = q1[k];
            float x0 = w0[k], x1 = w1[k], x2 = w2[k], x3 = w3[k];
            acc[0][0] += a0 * x0; acc[0][1] += a0 * x1; acc[0][2] += a0 * x2; acc[0][3] += a0 * x3;
            acc[1][0] += a1 * x0; acc[1][1] += a1 * x1; acc[1][2] += a1 * x2; acc[1][3] += a1 * x3;
        }
        #pragma unroll
        for (int rr = 0; rr < 2; rr++) {
            int r = r2 + rr;
            size_t pmoff = ((size_t)b * SL + i0 + r) * SL + j0 + c4;
            const int* mp = MSK + (size_t)b * SL * SL + (size_t)(i0 + r) * SL + j0 + c4;
            #pragma unroll
            for (int n = 0; n < 4; n++) {
                int idx = PM32[(pmoff + n) << pmshift];
                idx = min(max(idx, 0), NP);  // safety clamp
                float s = (acc[rr][n] + sSA[r * SA_STRIDE + idx]) * inv;
                if (mp[n] == 0) s = -1e9f;
                sS[r * SS_STRIDE + j0 + c4 + n] = s;
            }
        }
        __syncthreads();
    }

    // ==== softmax rows (warp per row) + write p_attn ====
    {
        const int wid = tid >> 5, lane = tid & 31;
        for (int r = wid; r < TI; r += 8) {
            float m = -1e30f;
            for (int j = lane; j < SL; j += 32) m = fmaxf(m, sS[r * SS_STRIDE + j]);
            #pragma unroll
            for (int o = 16; o; o >>= 1) m = fmaxf(m, __shfl_xor_sync(0xffffffffu, m, o));
            float sum = 0.f;
            for (int j = lane; j < SL; j += 32) {
                float e = __expf(sS[r * SS_STRIDE + j] - m);
                sS[r * SS_STRIDE + j] = e;
                sum += e;
            }
            #pragma unroll
            for (int o = 16; o; o >>= 1) sum += __shfl_xor_sync(0xffffffffu, sum, o);
            float rs = 1.f / sum;
            size_t pbase = (bh * SL + (size_t)(i0 + r)) * SL;
            for (int j = lane; j < SL; j += 32) {
                float pv = sS[r * SS_STRIDE + j] * rs;
                sS[r * SS_STRIDE + j] = pv;
                if (out_p) out_p[pbase + j] = pv;
            }
        }
    }
    __syncthreads();

    // ==== scatter p_attn into SV[16][1025] (reuse sSA) ====
    for (int t = tid; t < TI * SA_STRIDE; t += NT) sSA[t] = 0.f;
    __syncthreads();
    for (int t = tid; t < TI * SL; t += NT) {
        int r = t >> 9, j = t & (SL - 1);
        size_t pmoff = ((size_t)b * SL + i0 + r) * SL + j;
        int idx = PM32[pmoff << pmshift];
        idx = min(max(idx, 0), NP);  // safety clamp (prevents OOB SMEM atomics)
        atomicAdd(&sSA[r * SA_STRIDE + idx], sS[r * SS_STRIDE + j]);
    }
    __syncthreads();

    // ==== output: attn = P@V + SV@RV ====
    const int ro = (tid >> 5) * 2;   // 8 row-groups x 2 = 16 rows
    const int ko = (tid & 31) * 2;   // 32 col-groups x 2 = 64 cols
    float o00 = 0.f, o01 = 0.f, o10 = 0.f, o11 = 0.f;

    // Part A: P @ V
    for (int j0 = 0; j0 < SL; j0 += CHUNK) {
        for (int t = tid; t < CHUNK * HD; t += NT) {
            int j = t >> 6, k = t & 63;
            sBuf[j * BUF_STRIDE + k] = V[kvbase + (size_t)(j0 + j) * HD + k];
        }
        __syncthreads();
        #pragma unroll 8
        for (int j = 0; j < CHUNK; j++) {
            float p0v = sS[ro * SS_STRIDE + j0 + j];
            float p1v = sS[(ro + 1) * SS_STRIDE + j0 + j];
            float v0 = sBuf[j * BUF_STRIDE + ko];
            float v1 = sBuf[j * BUF_STRIDE + ko + 1];
            o00 += p0v * v0; o01 += p0v * v1;
            o10 += p1v * v0; o11 += p1v * v1;
        }
        __syncthreads();
    }

    // Part B: SV @ RV
    for (int p0 = 0; p0 < NP; p0 += CHUNK) {
        for (int t = tid; t < CHUNK * HD; t += NT) {
            int p = t >> 6, k = t & 63;
            sBuf[p * BUF_STRIDE + k] = RV[rbase + (size_t)(p0 + p) * HD + k];
        }
        __syncthreads();
        #pragma unroll 8
        for (int p = 0; p < CHUNK; p++) {
            float a0 = sSA[ro * SA_STRIDE + p0 + p];
            float a1 = sSA[(ro + 1) * SA_STRIDE + p0 + p];
            float v0 = sBuf[p * BUF_STRIDE + ko];
            float v1 = sBuf[p * BUF_STRIDE + ko + 1];
            o00 += a0 * v0; o01 += a0 * v1;
            o10 += a1 * v0; o11 += a1 * v1;
        }
        __syncthreads();
    }

    const size_t obase = (bh * SL + i0) * HD;
    out_attn[obase + (size_t)ro * HD + ko]           = o00;
    out_attn[obase + (size_t)ro * HD + ko + 1]       = o01;
    out_attn[obase + (size_t)(ro + 1) * HD + ko]     = o10;
    out_attn[obase + (size_t)(ro + 1) * HD + ko + 1] = o11;
}

extern "C" void kernel_launch(void* const* d_in, const int* in_sizes, int n_in,
                              void* d_out, int out_size)
{
    // Input binding: R4 confirmed insertion order (4M-element r_k/r_v at {3,4});
    // keep the in_sizes check as a safety net.
    int i4 = -1;
    for (int i = 0; i < n_in; i++) {
        if ((size_t)in_sizes[i] == R_ELEMS) { i4 = i; break; }
    }

    const float *Q, *K, *V, *RK, *RV;
    const int* PM32;
    const int* MSK;

    if (i4 == 4) {
        // alphabetical: key, mask, path_map, query, r_k, r_v, value
        K    = (const float*)d_in[0];
        MSK  = (const int*)d_in[1];
        PM32 = (const int*)d_in[2];
        Q    = (const float*)d_in[3];
        RK   = (const float*)d_in[4];
        RV   = (const float*)d_in[5];
        V    = (const float*)d_in[6];
    } else {
        // insertion order (confirmed): query, key, value, r_k, r_v, path_map, mask
        Q    = (const float*)d_in[0];
        K    = (const float*)d_in[1];
        V    = (const float*)d_in[2];
        RK   = (const float*)d_in[3];
        RV   = (const float*)d_in[4];
        PM32 = (const int*)d_in[5];
        MSK  = (const int*)d_in[6];
    }

    float* out = (float*)d_out;
    float* out_attn;
    float* out_p;
    if ((size_t)out_size >= ATTN_ELEMS + P_ELEMS) {
        out_attn = out;
        out_p = out + ATTN_ELEMS;
    } else if ((size_t)out_size == ATTN_ELEMS) {
        out_attn = out;
        out_p = nullptr;
    } else {
        // harness wants only p_attn: park attn_sum in scratch
        cudaGetSymbolAddress((void**)&out_attn, g_attn_scratch);
        out_p = out;
    }

    cudaFuncSetAttribute(rel_attn_kernel,
                         cudaFuncAttributeMaxDynamicSharedMemorySize, SMEM_BYTES);

    // Prepass: decide whether path_map is int32 (JAX default) or genuine int64.
    detect_pm_kernel<<<1, 256>>>(PM32);

    dim3 grid(SL / TI, NH, BS);
    rel_attn_kernel<<<grid, NT, SMEM_BYTES>>>(Q, K, V, RK, RV, PM32, MSK, out_attn, out_p);
}

// round 7
// speedup vs baseline: 1.4257x; 1.4257x over previous
#include <cuda_runtime.h>

// Problem shapes (fixed for this instance)
#define BS 8
#define NH 8
#define SL 512
#define HD 64
#define NP 1024

#define TI 16     // query rows per CTA
#define NT 512    // threads per CTA (16 warps)
#define CHUNK 128 // staging chunk (rows of K/V/r_k/r_v)

// SMEM layout (floats); strides multiple of 4 for float4, chosen to avoid conflicts
#define SQ_STRIDE 68
#define SA_STRIDE 1028
#define BUF_STRIDE 68
#define SS_STRIDE 516

#define SQ_OFF 0
#define SA_OFF (TI * SQ_STRIDE)                    // 1088
#define BUF_OFF (SA_OFF + TI * SA_STRIDE)          // 17536
#define SS_OFF (BUF_OFF + CHUNK * BUF_STRIDE)      // 26240
#define SMEM_FLOATS (SS_OFF + TI * SS_STRIDE)      // 34496
#define SMEM_BYTES (SMEM_FLOATS * 4)               // 137984 bytes

#define ATTN_ELEMS ((size_t)BS * NH * SL * HD)     // 2,097,152
#define P_ELEMS ((size_t)BS * NH * SL * SL)        // 16,777,216
#define R_ELEMS ((size_t)BS * NH * NP * HD)        // 4,194,304

__device__ float g_attn_scratch[ATTN_ELEMS];
__device__ int g_pm_is64;

// Detect whether path_map buffer is int64 (odd int32 words all zero) or int32.
__global__ void detect_pm_kernel(const int* __restrict__ pm32)
{
    __shared__ int any_nonzero;
    if (threadIdx.x == 0) any_nonzero = 0;
    __syncthreads();
    for (int i = threadIdx.x; i < 4096; i += blockDim.x) {
        if (pm32[2 * i + 1] != 0) any_nonzero = 1;
    }
    __syncthreads();
    if (threadIdx.x == 0) g_pm_is64 = (any_nonzero == 0) ? 1 : 0;
}

__global__ void __launch_bounds__(NT, 1)
rel_attn_kernel(const float* __restrict__ Q, const float* __restrict__ K,
                const float* __restrict__ V, const float* __restrict__ RK,
                const float* __restrict__ RV, const int* __restrict__ PM32,
                const int* __restrict__ MSK,
                float* __restrict__ out_attn, float* __restrict__ out_p)
{
    extern __shared__ float sm[];
    float* sQ   = sm + SQ_OFF;   // [TI][68]
    float* sSA  = sm + SA_OFF;   // [TI][1028] (cols 0..1024 used; col NP = zero row)
    float* sBuf = sm + BUF_OFF;  // [128][68]
    float* sS   = sm + SS_OFF;   // [TI][516]

    const int b = blockIdx.z, h = blockIdx.y;
    const int i0 = blockIdx.x * TI;
    const int tid = threadIdx.x;
    const int pmshift = g_pm_is64;

    const size_t bh = (size_t)b * NH + h;
    const size_t qbase  = (bh * SL + i0) * HD;
    const size_t kvbase = bh * SL * HD;
    const size_t rbase  = bh * NP * HD;

    // ---- stage Q tile (float4) ----
    {
        const float4* src = (const float4*)(Q + qbase);
        for (int t = tid; t < TI * (HD / 4); t += NT) {
            int r = t >> 4, k4 = t & 15;
            *(float4*)&sQ[r * SQ_STRIDE + k4 * 4] = src[r * 16 + k4];
        }
    }
    if (tid < TI) sSA[tid * SA_STRIDE + NP] = 0.f;
    __syncthreads();

    // dot-phase mapping: 4 rows x 1 col per thread over [16 x 128] chunk tile
    const int dcol = tid & 127;        // 0..127
    const int drow = (tid >> 7) * 4;   // 0,4,8,12 (warp-uniform)

    // ==== SA[16][1024] = Qtile @ RK^T ====
    for (int p0 = 0; p0 < NP; p0 += CHUNK) {
        const float4* src = (const float4*)(RK + rbase + (size_t)p0 * HD);
        for (int t = tid; t < CHUNK * (HD / 4); t += NT) {
            int p = t >> 4, k4 = t & 15;
            *(float4*)&sBuf[p * BUF_STRIDE + k4 * 4] = src[p * 16 + k4];
        }
        __syncthreads();
        float a0 = 0.f, a1 = 0.f, a2 = 0.f, a3 = 0.f;
        #pragma unroll
        for (int k = 0; k < HD; k += 4) {
            float4 wv = *(const float4*)&sBuf[dcol * BUF_STRIDE + k];
            float4 q0 = *(const float4*)&sQ[(drow + 0) * SQ_STRIDE + k];
            float4 q1 = *(const float4*)&sQ[(drow + 1) * SQ_STRIDE + k];
            float4 q2 = *(const float4*)&sQ[(drow + 2) * SQ_STRIDE + k];
            float4 q3 = *(const float4*)&sQ[(drow + 3) * SQ_STRIDE + k];
            a0 += q0.x*wv.x + q0.y*wv.y + q0.z*wv.z + q0.w*wv.w;
            a1 += q1.x*wv.x + q1.y*wv.y + q1.z*wv.z + q1.w*wv.w;
            a2 += q2.x*wv.x + q2.y*wv.y + q2.z*wv.z + q2.w*wv.w;
            a3 += q3.x*wv.x + q3.y*wv.y + q3.z*wv.z + q3.w*wv.w;
        }
        sSA[(drow + 0) * SA_STRIDE + p0 + dcol] = a0;
        sSA[(drow + 1) * SA_STRIDE + p0 + dcol] = a1;
        sSA[(drow + 2) * SA_STRIDE + p0 + dcol] = a2;
        sSA[(drow + 3) * SA_STRIDE + p0 + dcol] = a3;
        __syncthreads();
    }

    // ==== S[16][512] = Qtile @ K^T + gather(SA, path_map), scale, mask ====
    const float inv = 0.125f;
    for (int j0 = 0; j0 < SL; j0 += CHUNK) {
        const float4* src = (const float4*)(K + kvbase + (size_t)j0 * HD);
        for (int t = tid; t < CHUNK * (HD / 4); t += NT) {
            int j = t >> 4, k4 = t & 15;
            *(float4*)&sBuf[j * BUF_STRIDE + k4 * 4] = src[j * 16 + k4];
        }
        __syncthreads();
        float a0 = 0.f, a1 = 0.f, a2 = 0.f, a3 = 0.f;
        #pragma unroll
        for (int k = 0; k < HD; k += 4) {
            float4 wv = *(const float4*)&sBuf[dcol * BUF_STRIDE + k];
            float4 q0 = *(const float4*)&sQ[(drow + 0) * SQ_STRIDE + k];
            float4 q1 = *(const float4*)&sQ[(drow + 1) * SQ_STRIDE + k];
            float4 q2 = *(const float4*)&sQ[(drow + 2) * SQ_STRIDE + k];
            float4 q3 = *(const float4*)&sQ[(drow + 3) * SQ_STRIDE + k];
            a0 += q0.x*wv.x + q0.y*wv.y + q0.z*wv.z + q0.w*wv.w;
            a1 += q1.x*wv.x + q1.y*wv.y + q1.z*wv.z + q1.w*wv.w;
            a2 += q2.x*wv.x + q2.y*wv.y + q2.z*wv.z + q2.w*wv.w;
            a3 += q3.x*wv.x + q3.y*wv.y + q3.z*wv.z + q3.w*wv.w;
        }
        float acc[4] = {a0, a1, a2, a3};
        #pragma unroll
        for (int rr = 0; rr < 4; rr++) {
            int r = drow + rr;
            size_t pmoff = ((size_t)b * SL + i0 + r) * SL + j0 + dcol;
            int idx = PM32[pmoff << pmshift];
            idx = min(max(idx, 0), NP);
            float s = (acc[rr] + sSA[r * SA_STRIDE + idx]) * inv;
            if (MSK[(size_t)b * SL * SL + (size_t)(i0 + r) * SL + j0 + dcol] == 0) s = -1e9f;
            sS[r * SS_STRIDE + j0 + dcol] = s;
        }
        __syncthreads();
    }

    // ==== softmax: one warp per row (16 warps == 16 rows) + write p_attn ====
    {
        const int wid = tid >> 5, lane = tid & 31;
        const int r = wid;
        float m = -1e30f;
        for (int j = lane; j < SL; j += 32) m = fmaxf(m, sS[r * SS_STRIDE + j]);
        #pragma unroll
        for (int o = 16; o; o >>= 1) m = fmaxf(m, __shfl_xor_sync(0xffffffffu, m, o));
        float sum = 0.f;
        for (int j = lane; j < SL; j += 32) {
            float e = __expf(sS[r * SS_STRIDE + j] - m);
            sS[r * SS_STRIDE + j] = e;
            sum += e;
        }
        #pragma unroll
        for (int o = 16; o; o >>= 1) sum += __shfl_xor_sync(0xffffffffu, sum, o);
        float rs = 1.f / sum;
        size_t pbase = (bh * SL + (size_t)(i0 + r)) * SL;
        for (int j = lane; j < SL; j += 32) {
            float pv = sS[r * SS_STRIDE + j] * rs;
            sS[r * SS_STRIDE + j] = pv;
            if (out_p) out_p[pbase + j] = pv;
        }
    }
    __syncthreads();

    // ==== scatter p_attn into SV[16][1025-ish] (reuse sSA) ====
    for (int t = tid; t < TI * SA_STRIDE; t += NT) sSA[t] = 0.f;
    __syncthreads();
    for (int t = tid; t < TI * SL; t += NT) {
        int r = t >> 9, j = t & (SL - 1);
        size_t pmoff = ((size_t)b * SL + i0 + r) * SL + j;
        int idx = PM32[pmoff << pmshift];
        idx = min(max(idx, 0), NP);
        atomicAdd(&sSA[r * SA_STRIDE + idx], sS[r * SS_STRIDE + j]);
    }
    __syncthreads();

    // ==== output: attn = P@V + SV@RV ; 2 rows x 1 col per thread ====
    const int oko = tid & 63;          // 0..63 head-dim col
    const int oro = (tid >> 6) * 2;    // 0..14 step 2 (warp-uniform)
    float o0 = 0.f, o1 = 0.f;

    // Part A: P @ V
    for (int j0 = 0; j0 < SL; j0 += CHUNK) {
        const float4* src = (const float4*)(V + kvbase + (size_t)j0 * HD);
        for (int t = tid; t < CHUNK * (HD / 4); t += NT) {
            int j = t >> 4, k4 = t & 15;
            *(float4*)&sBuf[j * BUF_STRIDE + k4 * 4] = src[j * 16 + k4];
        }
        __syncthreads();
        #pragma unroll 8
        for (int j = 0; j < CHUNK; j += 4) {
            float4 p0 = *(const float4*)&sS[(oro + 0) * SS_STRIDE + j0 + j];
            float4 p1 = *(const float4*)&sS[(oro + 1) * SS_STRIDE + j0 + j];
            float v0 = sBuf[(j + 0) * BUF_STRIDE + oko];
            float v1 = sBuf[(j + 1) * BUF_STRIDE + oko];
            float v2 = sBuf[(j + 2) * BUF_STRIDE + oko];
            float v3 = sBuf[(j + 3) * BUF_STRIDE + oko];
            o0 += p0.x*v0 + p0.y*v1 + p0.z*v2 + p0.w*v3;
            o1 += p1.x*v0 + p1.y*v1 + p1.z*v2 + p1.w*v3;
        }
        __syncthreads();
    }

    // Part B: SV @ RV
    for (int p0 = 0; p0 < NP; p0 += CHUNK) {
        const float4* src = (const float4*)(RV + rbase + (size_t)p0 * HD);
        for (int t = tid; t < CHUNK * (HD / 4); t += NT) {
            int p = t >> 4, k4 = t & 15;
            *(float4*)&sBuf[p * BUF_STRIDE + k4 * 4] = src[p * 16 + k4];
        }
        __syncthreads();
        #pragma unroll 8
        for (int p = 0; p < CHUNK; p += 4) {
            float4 a0 = *(const float4*)&sSA[(oro + 0) * SA_STRIDE + p0 + p];
            float4 a1 = *(const float4*)&sSA[(oro + 1) * SA_STRIDE + p0 + p];
            float v0 = sBuf[(p + 0) * BUF_STRIDE + oko];
            float v1 = sBuf[(p + 1) * BUF_STRIDE + oko];
            float v2 = sBuf[(p + 2) * BUF_STRIDE + oko];
            float v3 = sBuf[(p + 3) * BUF_STRIDE + oko];
            o0 += a0.x*v0 + a0.y*v1 + a0.z*v2 + a0.w*v3;
            o1 += a1.x*v0 + a1.y*v1 + a1.z*v2 + a1.w*v3;
        }
        __syncthreads();
    }

    const size_t obase = (bh * SL + i0) * HD;
    out_attn[obase + (size_t)(oro + 0) * HD + oko] = o0;
    out_attn[obase + (size_t)(oro + 1) * HD + oko] = o1;
}

extern "C" void kernel_launch(void* const* d_in, const int* in_sizes, int n_in,
                              void* d_out, int out_size)
{
    int i4 = -1;
    for (int i = 0; i < n_in; i++) {
        if ((size_t)in_sizes[i] == R_ELEMS) { i4 = i; break; }
    }

    const float *Q, *K, *V, *RK, *RV;
    const int* PM32;
    const int* MSK;

    if (i4 == 4) {
        K    = (const float*)d_in[0];
        MSK  = (const int*)d_in[1];
        PM32 = (const int*)d_in[2];
        Q    = (const float*)d_in[3];
        RK   = (const float*)d_in[4];
        RV   = (const float*)d_in[5];
        V    = (const float*)d_in[6];
    } else {
        Q    = (const float*)d_in[0];
        K    = (const float*)d_in[1];
        V    = (const float*)d_in[2];
        RK   = (const float*)d_in[3];
        RV   = (const float*)d_in[4];
        PM32 = (const int*)d_in[5];
        MSK  = (const int*)d_in[6];
    }

    float* out = (float*)d_out;
    float* out_attn;
    float* out_p;
    if ((size_t)out_size >= ATTN_ELEMS + P_ELEMS) {
        out_attn = out;
        out_p = out + ATTN_ELEMS;
    } else if ((size_t)out_size == ATTN_ELEMS) {
        out_attn = out;
        out_p = nullptr;
    } else {
        cudaGetSymbolAddress((void**)&out_attn, g_attn_scratch);
        out_p = out;
    }

    cudaFuncSetAttribute(rel_attn_kernel,
                         cudaFuncAttributeMaxDynamicSharedMemorySize, SMEM_BYTES);

    detect_pm_kernel<<<1, 256>>>(PM32);

    dim3 grid(SL / TI, NH, BS);
    rel_attn_kernel<<<grid, NT, SMEM_BYTES>>>(Q, K, V, RK, RV, PM32, MSK, out_attn, out_p);
}

// round 9
// speedup vs baseline: 2.1449x; 1.5045x over previous
#include <cuda_runtime.h>

// Problem shapes (fixed for this instance)
#define BS 8
#define NH 8
#define SL 512
#define HD 64
#define NP 1024

#define TI 16     // query rows per CTA
#define NT 512    // threads per CTA (16 warps)
#define CHUNK 256 // staging chunk (rows of K/V/r_k/r_v)

// SMEM layout (floats); strides multiple of 4 for float4; stride%32=4 -> conflict-free
#define SQ_STRIDE 68
#define SA_STRIDE 1028
#define BUF_STRIDE 68
#define SS_STRIDE 516

#define SQ_OFF 0
#define SA_OFF (TI * SQ_STRIDE)                    // 1088
#define BUF_OFF (SA_OFF + TI * SA_STRIDE)          // 17536
#define SS_OFF (BUF_OFF + CHUNK * BUF_STRIDE)      // 34944
#define SMEM_FLOATS (SS_OFF + TI * SS_STRIDE)      // 43200
#define SMEM_BYTES (SMEM_FLOATS * 4)               // 172800 bytes

#define ATTN_ELEMS ((size_t)BS * NH * SL * HD)     // 2,097,152
#define P_ELEMS ((size_t)BS * NH * SL * SL)        // 16,777,216
#define R_ELEMS ((size_t)BS * NH * NP * HD)        // 4,194,304

__device__ float g_attn_scratch[ATTN_ELEMS];
__device__ int g_pm_is64;

// Detect whether path_map buffer is int64 (odd int32 words all zero) or int32.
__global__ void detect_pm_kernel(const int* __restrict__ pm32)
{
    __shared__ int any_nonzero;
    if (threadIdx.x == 0) any_nonzero = 0;
    __syncthreads();
    for (int i = threadIdx.x; i < 4096; i += blockDim.x) {
        if (pm32[2 * i + 1] != 0) any_nonzero = 1;
    }
    __syncthreads();
    if (threadIdx.x == 0) g_pm_is64 = (any_nonzero == 0) ? 1 : 0;
}

__global__ void __launch_bounds__(NT, 1)
rel_attn_kernel(const float* __restrict__ Q, const float* __restrict__ K,
                const float* __restrict__ V, const float* __restrict__ RK,
                const float* __restrict__ RV, const int* __restrict__ PM32,
                const int* __restrict__ MSK,
                float* __restrict__ out_attn, float* __restrict__ out_p)
{
    extern __shared__ float sm[];
    float* sQ   = sm + SQ_OFF;   // [TI][68]
    float* sSA  = sm + SA_OFF;   // [TI][1028] (cols 0..1024 used; col NP = zero row)
    float* sBuf = sm + BUF_OFF;  // [256][68]
    float* sS   = sm + SS_OFF;   // [TI][516]

    const int b = blockIdx.z, h = blockIdx.y;
    const int i0 = blockIdx.x * TI;
    const int tid = threadIdx.x;
    const int pmshift = g_pm_is64;

    const size_t bh = (size_t)b * NH + h;
    const size_t qbase  = (bh * SL + i0) * HD;
    const size_t kvbase = bh * SL * HD;
    const size_t rbase  = bh * NP * HD;

    // ---- stage Q tile (float4) ----
    {
        const float4* src = (const float4*)(Q + qbase);
        for (int t = tid; t < TI * (HD / 4); t += NT) {
            int r = t >> 4, k4 = t & 15;
            *(float4*)&sQ[r * SQ_STRIDE + k4 * 4] = src[r * 16 + k4];
        }
    }
    if (tid < TI) sSA[tid * SA_STRIDE + NP] = 0.f;
    __syncthreads();

    // dot-phase mapping over [16 x 256] chunk tile:
    //   each thread: 4 rows x 2 cols, cols strided by 128 (conflict-free)
    const int dc0  = tid & 127;        // col A: 0..127
    const int dc1  = dc0 + 128;        // col B: 128..255
    const int drow = (tid >> 7) * 4;   // 0,4,8,12 (warp-uniform)

    // ==== SA[16][1024] = Qtile @ RK^T ====
    for (int p0 = 0; p0 < NP; p0 += CHUNK) {
        const float4* src = (const float4*)(RK + rbase + (size_t)p0 * HD);
        for (int t = tid; t < CHUNK * (HD / 4); t += NT) {
            int p = t >> 4, k4 = t & 15;
            *(float4*)&sBuf[p * BUF_STRIDE + k4 * 4] = src[p * 16 + k4];
        }
        __syncthreads();
        float acc[4][2] = {};
        #pragma unroll
        for (int k = 0; k < HD; k += 4) {
            float4 w0 = *(const float4*)&sBuf[dc0 * BUF_STRIDE + k];
            float4 w1 = *(const float4*)&sBuf[dc1 * BUF_STRIDE + k];
            #pragma unroll
            for (int r = 0; r < 4; r++) {
                float4 q = *(const float4*)&sQ[(drow + r) * SQ_STRIDE + k];
                acc[r][0] += q.x*w0.x + q.y*w0.y + q.z*w0.z + q.w*w0.w;
                acc[r][1] += q.x*w1.x + q.y*w1.y + q.z*w1.z + q.w*w1.w;
            }
        }
        #pragma unroll
        for (int r = 0; r < 4; r++) {
            sSA[(drow + r) * SA_STRIDE + p0 + dc0] = acc[r][0];
            sSA[(drow + r) * SA_STRIDE + p0 + dc1] = acc[r][1];
        }
        __syncthreads();
    }

    // ==== S[16][512] = Qtile @ K^T + gather(SA, path_map), scale, mask ====
    const float inv = 0.125f;
    for (int j0 = 0; j0 < SL; j0 += CHUNK) {
        const float4* src = (const float4*)(K + kvbase + (size_t)j0 * HD);
        for (int t = tid; t < CHUNK * (HD / 4); t += NT) {
            int j = t >> 4, k4 = t & 15;
            *(float4*)&sBuf[j * BUF_STRIDE + k4 * 4] = src[j * 16 + k4];
        }
        __syncthreads();
        float acc[4][2] = {};
        #pragma unroll
        for (int k = 0; k < HD; k += 4) {
            float4 w0 = *(const float4*)&sBuf[dc0 * BUF_STRIDE + k];
            float4 w1 = *(const float4*)&sBuf[dc1 * BUF_STRIDE + k];
            #pragma unroll
            for (int r = 0; r < 4; r++) {
                float4 q = *(const float4*)&sQ[(drow + r) * SQ_STRIDE + k];
                acc[r][0] += q.x*w0.x + q.y*w0.y + q.z*w0.z + q.w*w0.w;
                acc[r][1] += q.x*w1.x + q.y*w1.y + q.z*w1.z + q.w*w1.w;
            }
        }
        #pragma unroll
        for (int r = 0; r < 4; r++) {
            int row = drow + r;
            size_t prow = ((size_t)b * SL + i0 + row) * SL;
            const int* mrow = MSK + (size_t)b * SL * SL + (size_t)(i0 + row) * SL;
            #pragma unroll
            for (int c = 0; c < 2; c++) {
                int col = j0 + (c ? dc1 : dc0);
                int idx = PM32[(prow + col) << pmshift];
                idx = min(max(idx, 0), NP);
                float s = (acc[r][c] + sSA[row * SA_STRIDE + idx]) * inv;
                if (mrow[col] == 0) s = -1e9f;
                sS[row * SS_STRIDE + col] = s;
            }
        }
        __syncthreads();
    }

    // ==== softmax: one warp per row (16 warps == 16 rows) + write p_attn ====
    {
        const int wid = tid >> 5, lane = tid & 31;
        const int r = wid;
        float m = -1e30f;
        for (int j = lane; j < SL; j += 32) m = fmaxf(m, sS[r * SS_STRIDE + j]);
        #pragma unroll
        for (int o = 16; o; o >>= 1) m = fmaxf(m, __shfl_xor_sync(0xffffffffu, m, o));
        float sum = 0.f;
        for (int j = lane; j < SL; j += 32) {
            float e = __expf(sS[r * SS_STRIDE + j] - m);
            sS[r * SS_STRIDE + j] = e;
            sum += e;
        }
        #pragma unroll
        for (int o = 16; o; o >>= 1) sum += __shfl_xor_sync(0xffffffffu, sum, o);
        float rs = 1.f / sum;
        size_t pbase = (bh * SL + (size_t)(i0 + r)) * SL;
        for (int j = lane; j < SL; j += 32) {
            float pv = sS[r * SS_STRIDE + j] * rs;
            sS[r * SS_STRIDE + j] = pv;
            if (out_p) out_p[pbase + j] = pv;
        }
    }
    __syncthreads();

    // ==== scatter p_attn into SV (reuse sSA) ====
    for (int t = tid; t < TI * SA_STRIDE; t += NT) sSA[t] = 0.f;
    __syncthreads();
    for (int t = tid; t < TI * SL; t += NT) {
        int r = t >> 9, j = t & (SL - 1);
        size_t pmoff = ((size_t)b * SL + i0 + r) * SL + j;
        int idx = PM32[pmoff << pmshift];
        idx = min(max(idx, 0), NP);
        atomicAdd(&sSA[r * SA_STRIDE + idx], sS[r * SS_STRIDE + j]);
    }
    __syncthreads();

    // ==== output: attn = P@V + SV@RV ; 2 rows x 1 col per thread ====
    const int oko = tid & 63;          // head-dim col
    const int oro = (tid >> 6) * 2;    // row pair (warp-uniform)
    float o0 = 0.f, o1 = 0.f;

    // Part A: P @ V   (512 rows -> 2 chunks)
    for (int j0 = 0; j0 < SL; j0 += CHUNK) {
        const float4* src = (const float4*)(V + kvbase + (size_t)j0 * HD);
        for (int t = tid; t < CHUNK * (HD / 4); t += NT) {
            int j = t >> 4, k4 = t & 15;
            *(float4*)&sBuf[j * BUF_STRIDE + k4 * 4] = src[j * 16 + k4];
        }
        __syncthreads();
        #pragma unroll 8
        for (int j = 0; j < CHUNK; j += 4) {
            float4 p0 = *(const float4*)&sS[(oro + 0) * SS_STRIDE + j0 + j];
            float4 p1 = *(const float4*)&sS[(oro + 1) * SS_STRIDE + j0 + j];
            float v0 = sBuf[(j + 0) * BUF_STRIDE + oko];
            float v1 = sBuf[(j + 1) * BUF_STRIDE + oko];
            float v2 = sBuf[(j + 2) * BUF_STRIDE + oko];
            float v3 = sBuf[(j + 3) * BUF_STRIDE + oko];
            o0 += p0.x*v0 + p0.y*v1 + p0.z*v2 + p0.w*v3;
            o1 += p1.x*v0 + p1.y*v1 + p1.z*v2 + p1.w*v3;
        }
        __syncthreads();
    }

    // Part B: SV @ RV  (1024 rows -> 4 chunks)
    for (int p0 = 0; p0 < NP; p0 += CHUNK) {
        const float4* src = (const float4*)(RV + rbase + (size_t)p0 * HD);
        for (int t = tid; t < CHUNK * (HD / 4); t += NT) {
            int p = t >> 4, k4 = t & 15;
            *(float4*)&sBuf[p * BUF_STRIDE + k4 * 4] = src[p * 16 + k4];
        }
        __syncthreads();
        #pragma unroll 8
        for (int p = 0; p < CHUNK; p += 4) {
            float4 a0 = *(const float4*)&sSA[(oro + 0) * SA_STRIDE + p0 + p];
            float4 a1 = *(const float4*)&sSA[(oro + 1) * SA_STRIDE + p0 + p];
            float v0 = sBuf[(p + 0) * BUF_STRIDE + oko];
            float v1 = sBuf[(p + 1) * BUF_STRIDE + oko];
            float v2 = sBuf[(p + 2) * BUF_STRIDE + oko];
            float v3 = sBuf[(p + 3) * BUF_STRIDE + oko];
            o0 += a0.x*v0 + a0.y*v1 + a0.z*v2 + a0.w*v3;
            o1 += a1.x*v0 + a1.y*v1 + a1.z*v2 + a1.w*v3;
        }
        __syncthreads();
    }

    const size_t obase = (bh * SL + i0) * HD;
    out_attn[obase + (size_t)(oro + 0) * HD + oko] = o0;
    out_attn[obase + (size_t)(oro + 1) * HD + oko] = o1;
}

extern "C" void kernel_launch(void* const* d_in, const int* in_sizes, int n_in,
                              void* d_out, int out_size)
{
    int i4 = -1;
    for (int i = 0; i < n_in; i++) {
        if ((size_t)in_sizes[i] == R_ELEMS) { i4 = i; break; }
    }

    const float *Q, *K, *V, *RK, *RV;
    const int* PM32;
    const int* MSK;

    if (i4 == 4) {
        K    = (const float*)d_in[0];
        MSK  = (const int*)d_in[1];
        PM32 = (const int*)d_in[2];
        Q    = (const float*)d_in[3];
        RK   = (const float*)d_in[4];
        RV   = (const float*)d_in[5];
        V    = (const float*)d_in[6];
    } else {
        Q    = (const float*)d_in[0];
        K    = (const float*)d_in[1];
        V    = (const float*)d_in[2];
        RK   = (const float*)d_in[3];
        RV   = (const float*)d_in[4];
        PM32 = (const int*)d_in[5];
        MSK  = (const int*)d_in[6];
    }

    float* out = (float*)d_out;
    float* out_attn;
    float* out_p;
    if ((size_t)out_size >= ATTN_ELEMS + P_ELEMS) {
        out_attn = out;
        out_p = out + ATTN_ELEMS;
    } else if ((size_t)out_size == ATTN_ELEMS) {
        out_attn = out;
        out_p = nullptr;
    } else {
        cudaGetSymbolAddress((void**)&out_attn, g_attn_scratch);
        out_p = out;
    }

    cudaFuncSetAttribute(rel_attn_kernel,
                         cudaFuncAttributeMaxDynamicSharedMemorySize, SMEM_BYTES);

    detect_pm_kernel<<<1, 256>>>(PM32);

    dim3 grid(SL / TI, NH, BS);
    rel_attn_kernel<<<grid, NT, SMEM_BYTES>>>(Q, K, V, RK, RV, PM32, MSK, out_attn, out_p);
}

// round 11
// speedup vs baseline: 2.4852x; 1.1587x over previous
#include <cuda_runtime.h>

// Problem shapes (fixed for this instance)
#define BS 8
#define NH 8
#define SL 512
#define HD 64
#define NP 1024

#define TI 16     // query rows per CTA
#define NT 512    // threads per CTA (16 warps)
#define CHUNK 256 // staging chunk (rows of K/V/r_k/r_v)

// SMEM layout (floats); strides multiple of 4 for float4; stride%32=4 -> conflict-free
#define SQ_STRIDE 68
#define SA_STRIDE 1028
#define BUF_STRIDE 68
#define SS_STRIDE 516

#define SQ_OFF 0
#define SA_OFF (TI * SQ_STRIDE)                    // 1088
#define BUF_OFF (SA_OFF + TI * SA_STRIDE)          // 17536
#define SS_OFF (BUF_OFF + CHUNK * BUF_STRIDE)      // 34944
#define SMEM_FLOATS (SS_OFF + TI * SS_STRIDE)      // 43200
#define SMEM_BYTES (SMEM_FLOATS * 4)               // 172800 bytes

#define ATTN_ELEMS ((size_t)BS * NH * SL * HD)     // 2,097,152
#define P_ELEMS ((size_t)BS * NH * SL * SL)        // 16,777,216
#define R_ELEMS ((size_t)BS * NH * NP * HD)        // 4,194,304

__device__ float g_attn_scratch[ATTN_ELEMS];
__device__ int g_pm_is64;

// Detect whether path_map buffer is int64 (odd int32 words all zero) or int32.
__global__ void detect_pm_kernel(const int* __restrict__ pm32)
{
    __shared__ int any_nonzero;
    if (threadIdx.x == 0) any_nonzero = 0;
    __syncthreads();
    for (int i = threadIdx.x; i < 4096; i += blockDim.x) {
        if (pm32[2 * i + 1] != 0) any_nonzero = 1;
    }
    __syncthreads();
    if (threadIdx.x == 0) g_pm_is64 = (any_nonzero == 0) ? 1 : 0;
}

__global__ void __launch_bounds__(NT, 1)
rel_attn_kernel(const float* __restrict__ Q, const float* __restrict__ K,
                const float* __restrict__ V, const float* __restrict__ RK,
                const float* __restrict__ RV, const int* __restrict__ PM32,
                const int* __restrict__ MSK,
                float* __restrict__ out_attn, float* __restrict__ out_p)
{
    extern __shared__ float sm[];
    float* sQ   = sm + SQ_OFF;   // [TI][68]
    float* sSA  = sm + SA_OFF;   // [TI][1028] (cols 0..1024 used; col NP = zero row)
    float* sBuf = sm + BUF_OFF;  // [256][68]; head reused as psum[4][16][68]
    float* sS   = sm + SS_OFF;   // [TI][516]

    const int b = blockIdx.z, h = blockIdx.y;
    const int i0 = blockIdx.x * TI;
    const int tid = threadIdx.x;
    const int pmshift = g_pm_is64;

    const size_t bh = (size_t)b * NH + h;
    const size_t qbase  = (bh * SL + i0) * HD;
    const size_t kvbase = bh * SL * HD;
    const size_t rbase  = bh * NP * HD;

    // ---- stage Q tile (float4) ----
    {
        const float4* src = (const float4*)(Q + qbase);
        for (int t = tid; t < TI * (HD / 4); t += NT) {
            int r = t >> 4, k4 = t & 15;
            *(float4*)&sQ[r * SQ_STRIDE + k4 * 4] = src[r * 16 + k4];
        }
    }
    if (tid < TI) sSA[tid * SA_STRIDE + NP] = 0.f;
    __syncthreads();

    // dot-phase mapping over [16 x 256] chunk tile:
    //   each thread: 4 rows x 2 cols, cols strided by 128 (conflict-free)
    const int dc0  = tid & 127;        // col A: 0..127
    const int dc1  = dc0 + 128;        // col B: 128..255
    const int drow = (tid >> 7) * 4;   // 0,4,8,12 (warp-uniform)

    // ==== SA[16][1024] = Qtile @ RK^T ====
    for (int p0 = 0; p0 < NP; p0 += CHUNK) {
        const float4* src = (const float4*)(RK + rbase + (size_t)p0 * HD);
        for (int t = tid; t < CHUNK * (HD / 4); t += NT) {
            int p = t >> 4, k4 = t & 15;
            *(float4*)&sBuf[p * BUF_STRIDE + k4 * 4] = src[p * 16 + k4];
        }
        __syncthreads();
        float acc[4][2] = {};
        #pragma unroll
        for (int k = 0; k < HD; k += 4) {
            float4 w0 = *(const float4*)&sBuf[dc0 * BUF_STRIDE + k];
            float4 w1 = *(const float4*)&sBuf[dc1 * BUF_STRIDE + k];
            #pragma unroll
            for (int r = 0; r < 4; r++) {
                float4 q = *(const float4*)&sQ[(drow + r) * SQ_STRIDE + k];
                acc[r][0] += q.x*w0.x + q.y*w0.y + q.z*w0.z + q.w*w0.w;
                acc[r][1] += q.x*w1.x + q.y*w1.y + q.z*w1.z + q.w*w1.w;
            }
        }
        #pragma unroll
        for (int r = 0; r < 4; r++) {
            sSA[(drow + r) * SA_STRIDE + p0 + dc0] = acc[r][0];
            sSA[(drow + r) * SA_STRIDE + p0 + dc1] = acc[r][1];
        }
        __syncthreads();
    }

    // ==== S[16][512] = Qtile @ K^T + gather(SA, path_map), scale, mask ====
    const float inv = 0.125f;
    for (int j0 = 0; j0 < SL; j0 += CHUNK) {
        const float4* src = (const float4*)(K + kvbase + (size_t)j0 * HD);
        for (int t = tid; t < CHUNK * (HD / 4); t += NT) {
            int j = t >> 4, k4 = t & 15;
            *(float4*)&sBuf[j * BUF_STRIDE + k4 * 4] = src[j * 16 + k4];
        }
        __syncthreads();
        float acc[4][2] = {};
        #pragma unroll
        for (int k = 0; k < HD; k += 4) {
            float4 w0 = *(const float4*)&sBuf[dc0 * BUF_STRIDE + k];
            float4 w1 = *(const float4*)&sBuf[dc1 * BUF_STRIDE + k];
            #pragma unroll
            for (int r = 0; r < 4; r++) {
                float4 q = *(const float4*)&sQ[(drow + r) * SQ_STRIDE + k];
                acc[r][0] += q.x*w0.x + q.y*w0.y + q.z*w0.z + q.w*w0.w;
                acc[r][1] += q.x*w1.x + q.y*w1.y + q.z*w1.z + q.w*w1.w;
            }
        }
        #pragma unroll
        for (int r = 0; r < 4; r++) {
            int row = drow + r;
            size_t prow = ((size_t)b * SL + i0 + row) * SL;
            const int* mrow = MSK + (size_t)b * SL * SL + (size_t)(i0 + row) * SL;
            #pragma unroll
            for (int c = 0; c < 2; c++) {
                int col = j0 + (c ? dc1 : dc0);
                int idx = PM32[(prow + col) << pmshift];
                idx = min(max(idx, 0), NP);
                float s = (acc[r][c] + sSA[row * SA_STRIDE + idx]) * inv;
                if (mrow[col] == 0) s = -1e9f;
                sS[row * SS_STRIDE + col] = s;
            }
        }
        __syncthreads();
    }

    // ==== softmax: one warp per row (16 warps == 16 rows) + write p_attn ====
    {
        const int wid = tid >> 5, lane = tid & 31;
        const int r = wid;
        float m = -1e30f;
        for (int j = lane; j < SL; j += 32) m = fmaxf(m, sS[r * SS_STRIDE + j]);
        #pragma unroll
        for (int o = 16; o; o >>= 1) m = fmaxf(m, __shfl_xor_sync(0xffffffffu, m, o));
        float sum = 0.f;
        for (int j = lane; j < SL; j += 32) {
            float e = __expf(sS[r * SS_STRIDE + j] - m);
            sS[r * SS_STRIDE + j] = e;
            sum += e;
        }
        #pragma unroll
        for (int o = 16; o; o >>= 1) sum += __shfl_xor_sync(0xffffffffu, sum, o);
        float rs = 1.f / sum;
        size_t pbase = (bh * SL + (size_t)(i0 + r)) * SL;
        for (int j = lane; j < SL; j += 32) {
            float pv = sS[r * SS_STRIDE + j] * rs;
            sS[r * SS_STRIDE + j] = pv;
            if (out_p) out_p[pbase + j] = pv;
        }
    }
    __syncthreads();

    // ==== scatter p_attn into SV (reuse sSA) ====
    for (int t = tid; t < TI * SA_STRIDE; t += NT) sSA[t] = 0.f;
    __syncthreads();
    for (int t = tid; t < TI * SL; t += NT) {
        int r = t >> 9, j = t & (SL - 1);
        size_t pmoff = ((size_t)b * SL + i0 + r) * SL + j;
        int idx = PM32[pmoff << pmshift];
        idx = min(max(idx, 0), NP);
        atomicAdd(&sSA[r * SA_STRIDE + idx], sS[r * SS_STRIDE + j]);
    }
    __syncthreads();

    // ==== output: attn = P@V + SV@RV ====
    // thread tile: 2 rows x 4 cols, 4-way j-split over each 256-row chunk.
    const int ocg = (tid & 15) * 4;        // col base: 0,4,...,60
    const int orp = ((tid >> 4) & 7) * 2;  // row base: 0,2,...,14
    const int ojs = tid >> 7;              // j-split 0..3 (64 rows each per chunk)
    float o00=0.f,o01=0.f,o02=0.f,o03=0.f;
    float o10=0.f,o11=0.f,o12=0.f,o13=0.f;

    // Part A: P @ V   (512 rows -> 2 chunks)
    for (int j0 = 0; j0 < SL; j0 += CHUNK) {
        const float4* src = (const float4*)(V + kvbase + (size_t)j0 * HD);
        for (int t = tid; t < CHUNK * (HD / 4); t += NT) {
            int j = t >> 4, k4 = t & 15;
            *(float4*)&sBuf[j * BUF_STRIDE + k4 * 4] = src[j * 16 + k4];
        }
        __syncthreads();
        const int jlo = ojs * 64, jhi = jlo + 64;
        #pragma unroll 4
        for (int j = jlo; j < jhi; j += 4) {
            float4 p0 = *(const float4*)&sS[(orp + 0) * SS_STRIDE + j0 + j];
            float4 p1 = *(const float4*)&sS[(orp + 1) * SS_STRIDE + j0 + j];
            float4 v0 = *(const float4*)&sBuf[(j + 0) * BUF_STRIDE + ocg];
            float4 v1 = *(const float4*)&sBuf[(j + 1) * BUF_STRIDE + ocg];
            float4 v2 = *(const float4*)&sBuf[(j + 2) * BUF_STRIDE + ocg];
            float4 v3 = *(const float4*)&sBuf[(j + 3) * BUF_STRIDE + ocg];
            o00 += p0.x*v0.x + p0.y*v1.x + p0.z*v2.x + p0.w*v3.x;
            o01 += p0.x*v0.y + p0.y*v1.y + p0.z*v2.y + p0.w*v3.y;
            o02 += p0.x*v0.z + p0.y*v1.z + p0.z*v2.z + p0.w*v3.z;
            o03 += p0.x*v0.w + p0.y*v1.w + p0.z*v2.w + p0.w*v3.w;
            o10 += p1.x*v0.x + p1.y*v1.x + p1.z*v2.x + p1.w*v3.x;
            o11 += p1.x*v0.y + p1.y*v1.y + p1.z*v2.y + p1.w*v3.y;
            o12 += p1.x*v0.z + p1.y*v1.z + p1.z*v2.z + p1.w*v3.z;
            o13 += p1.x*v0.w + p1.y*v1.w + p1.z*v2.w + p1.w*v3.w;
        }
        __syncthreads();
    }

    // Part B: SV @ RV  (1024 rows -> 4 chunks)
    for (int p0 = 0; p0 < NP; p0 += CHUNK) {
        const float4* src = (const float4*)(RV + rbase + (size_t)p0 * HD);
        for (int t = tid; t < CHUNK * (HD / 4); t += NT) {
            int p = t >> 4, k4 = t & 15;
            *(float4*)&sBuf[p * BUF_STRIDE + k4 * 4] = src[p * 16 + k4];
        }
        __syncthreads();
        const int jlo = ojs * 64, jhi = jlo + 64;
        #pragma unroll 4
        for (int p = jlo; p < jhi; p += 4) {
            float4 a0 = *(const float4*)&sSA[(orp + 0) * SA_STRIDE + p0 + p];
            float4 a1 = *(const float4*)&sSA[(orp + 1) * SA_STRIDE + p0 + p];
            float4 v0 = *(const float4*)&sBuf[(p + 0) * BUF_STRIDE + ocg];
            float4 v1 = *(const float4*)&sBuf[(p + 1) * BUF_STRIDE + ocg];
            float4 v2 = *(const float4*)&sBuf[(p + 2) * BUF_STRIDE + ocg];
            float4 v3 = *(const float4*)&sBuf[(p + 3) * BUF_STRIDE + ocg];
            o00 += a0.x*v0.x + a0.y*v1.x + a0.z*v2.x + a0.w*v3.x;
            o01 += a0.x*v0.y + a0.y*v1.y + a0.z*v2.y + a0.w*v3.y;
            o02 += a0.x*v0.z + a0.y*v1.z + a0.z*v2.z + a0.w*v3.z;
            o03 += a0.x*v0.w + a0.y*v1.w + a0.z*v2.w + a0.w*v3.w;
            o10 += a1.x*v0.x + a1.y*v1.x + a1.z*v2.x + a1.w*v3.x;
            o11 += a1.x*v0.y + a1.y*v1.y + a1.z*v2.y + a1.w*v3.y;
            o12 += a1.x*v0.z + a1.y*v1.z + a1.z*v2.z + a1.w*v3.z;
            o13 += a1.x*v0.w + a1.y*v1.w + a1.z*v2.w + a1.w*v3.w;
        }
        __syncthreads();
    }

    // ---- reduce the 4 j-split partials via psum overlay in sBuf ----
    // psum[js][row][col] at sBuf + js*16*68 + row*68 + col (4*16*68 = 4352 floats)
    {
        float* psum = sBuf;
        float* base0 = psum + (ojs * TI + orp) * 68 + ocg;
        *(float4*)&base0[0]  = make_float4(o00, o01, o02, o03);
        *(float4*)&base0[68] = make_float4(o10, o11, o12, o13);
        __syncthreads();
        const size_t obase = (bh * SL + i0) * HD;
        for (int e = tid; e < TI * HD; e += NT) {
            int r = e >> 6, c = e & 63;
            float s = psum[(0 * TI + r) * 68 + c]
                    + psum[(1 * TI + r) * 68 + c]
                    + psum[(2 * TI + r) * 68 + c]
                    + psum[(3 * TI + r) * 68 + c];
            out_attn[obase + (size_t)r * HD + c] = s;
        }
    }
}

extern "C" void kernel_launch(void* const* d_in, const int* in_sizes, int n_in,
                              void* d_out, int out_size)
{
    int i4 = -1;
    for (int i = 0; i < n_in; i++) {
        if ((size_t)in_sizes[i] == R_ELEMS) { i4 = i; break; }
    }

    const float *Q, *K, *V, *RK, *RV;
    const int* PM32;
    const int* MSK;

    if (i4 == 4) {
        K    = (const float*)d_in[0];
        MSK  = (const int*)d_in[1];
        PM32 = (const int*)d_in[2];
        Q    = (const float*)d_in[3];
        RK   = (const float*)d_in[4];
        RV   = (const float*)d_in[5];
        V    = (const float*)d_in[6];
    } else {
        Q    = (const float*)d_in[0];
        K    = (const float*)d_in[1];
        V    = (const float*)d_in[2];
        RK   = (const float*)d_in[3];
        RV   = (const float*)d_in[4];
        PM32 = (const int*)d_in[5];
        MSK  = (const int*)d_in[6];
    }

    float* out = (float*)d_out;
    float* out_attn;
    float* out_p;
    if ((size_t)out_size >= ATTN_ELEMS + P_ELEMS) {
        out_attn = out;
        out_p = out + ATTN_ELEMS;
    } else if ((size_t)out_size == ATTN_ELEMS) {
        out_attn = out;
        out_p = nullptr;
    } else {
        cudaGetSymbolAddress((void**)&out_attn, g_attn_scratch);
        out_p = out;
    }

    cudaFuncSetAttribute(rel_attn_kernel,
                         cudaFuncAttributeMaxDynamicSharedMemorySize, SMEM_BYTES);

    detect_pm_kernel<<<1, 256>>>(PM32);

    dim3 grid(SL / TI, NH, BS);
    rel_attn_kernel<<<grid, NT, SMEM_BYTES>>>(Q, K, V, RK, RV, PM32, MSK, out_attn, out_p);
}

// round 13
// speedup vs baseline: 2.7017x; 1.0871x over previous
#include <cuda_runtime.h>
#include <cstdint>

// Problem shapes (fixed for this instance)
#define BS 8
#define NH 8
#define SL 512
#define HD 64
#define NP 1024

#define TI 16     // query rows per CTA (fused kernel)
#define NT 512    // threads per CTA (16 warps)
#define CHUNK 256 // staging chunk (rows of K/V/r_v)

// SMEM layout (floats); strides multiple of 4 for float4; stride%32=4 -> conflict-free
#define SQ_STRIDE 68
#define SA_STRIDE 1028
#define BUF_STRIDE 68
#define SS_STRIDE 516

#define SQ_OFF 0
#define SA_OFF (TI * SQ_STRIDE)                    // 1088
#define BUF_OFF (SA_OFF + TI * SA_STRIDE)          // 17536
#define SS_OFF (BUF_OFF + CHUNK * BUF_STRIDE)      // 34944
#define SMEM_FLOATS (SS_OFF + TI * SS_STRIDE)      // 43200
#define SMEM_BYTES (SMEM_FLOATS * 4)               // 172800 bytes

#define ATTN_ELEMS ((size_t)BS * NH * SL * HD)     // 2,097,152
#define P_ELEMS ((size_t)BS * NH * SL * SL)        // 16,777,216
#define R_ELEMS ((size_t)BS * NH * NP * HD)        // 4,194,304

__device__ float g_attn_scratch[ATTN_ELEMS];
__device__ int g_pm_is64;
// Precomputed relation scores: [bh][i][p], 64*512*1024 floats = 134 MB
__device__ float g_score_all[(size_t)BS * NH * SL * NP];

// Detect whether path_map buffer is int64 (odd int32 words all zero) or int32.
__global__ void detect_pm_kernel(const int* __restrict__ pm32)
{
    __shared__ int any_nonzero;
    if (threadIdx.x == 0) any_nonzero = 0;
    __syncthreads();
    for (int i = threadIdx.x; i < 4096; i += blockDim.x) {
        if (pm32[2 * i + 1] != 0) any_nonzero = 1;
    }
    __syncthreads();
    if (threadIdx.x == 0) g_pm_is64 = (any_nonzero == 0) ? 1 : 0;
}

// ===========================================================================
// Kernel A: g_score_all[bh][i][p] = sum_k Q[bh,i,k] * RK[bh,p,k]
// tf32 mma.sync with 3xTF32 compensation (Ahi*Bhi + Ahi*Blo + Alo*Bhi).
// CTA tile: 64 (i) x 128 (p), K=64 single stage. 8 warps, warp tile 32x32.
// ===========================================================================
#define GA_IT 64
#define GA_PT 128
#define GA_LD 68
#define GA_SAH 0
#define GA_SAL (GA_IT * GA_LD)
#define GA_SBH (2 * GA_IT * GA_LD)
#define GA_SBL (2 * GA_IT * GA_LD + GA_PT * GA_LD)
#define GA_SMEM_FLOATS (2 * GA_IT * GA_LD + 2 * GA_PT * GA_LD)   // 26112
#define GA_SMEM_BYTES (GA_SMEM_FLOATS * 4)                        // 104448

__device__ __forceinline__ float f_tf32(float x) {
    uint32_t r;
    asm("cvt.rna.tf32.f32 %0, %1;" : "=r"(r) : "f"(x));
    return __uint_as_float(r);
}

#define MMA_TF32(d, a, b) \
    asm volatile("mma.sync.aligned.m16n8k8.row.col.f32.tf32.tf32.f32 " \
                 "{%0,%1,%2,%3},{%4,%5,%6,%7},{%8,%9},{%0,%1,%2,%3};" \
                 : "+f"((d)[0]), "+f"((d)[1]), "+f"((d)[2]), "+f"((d)[3]) \
                 : "r"((a)[0]), "r"((a)[1]), "r"((a)[2]), "r"((a)[3]), \
                   "r"((b)[0]), "r"((b)[1]))

__global__ void __launch_bounds__(256, 1)
score_all_kernel(const float* __restrict__ Q, const float* __restrict__ RK)
{
    extern __shared__ float sg[];
    float* sAh = sg + GA_SAH;  // [64][68]
    float* sAl = sg + GA_SAL;
    float* sBh = sg + GA_SBH;  // [128][68]
    float* sBl = sg + GA_SBL;

    const int bh  = blockIdx.z;
    const int it0 = blockIdx.y * GA_IT;
    const int pt0 = blockIdx.x * GA_PT;
    const int tid = threadIdx.x;

    const float* qsrc = Q + ((size_t)bh * SL + it0) * HD;
    const float* rsrc = RK + ((size_t)bh * NP + pt0) * HD;

    // stage A (Q tile 64x64) with hi/lo tf32 split
    for (int t = tid; t < GA_IT * (HD / 4); t += 256) {
        int r = t >> 4, k4 = (t & 15) * 4;
        float4 v = *(const float4*)(qsrc + (size_t)r * HD + k4);
        float hx = f_tf32(v.x), hy = f_tf32(v.y), hz = f_tf32(v.z), hw = f_tf32(v.w);
        sAh[r * GA_LD + k4 + 0] = hx; sAl[r * GA_LD + k4 + 0] = f_tf32(v.x - hx);
        sAh[r * GA_LD + k4 + 1] = hy; sAl[r * GA_LD + k4 + 1] = f_tf32(v.y - hy);
        sAh[r * GA_LD + k4 + 2] = hz; sAl[r * GA_LD + k4 + 2] = f_tf32(v.z - hz);
        sAh[r * GA_LD + k4 + 3] = hw; sAl[r * GA_LD + k4 + 3] = f_tf32(v.w - hw);
    }
    // stage B (RK tile 128x64)
    for (int t = tid; t < GA_PT * (HD / 4); t += 256) {
        int r = t >> 4, k4 = (t & 15) * 4;
        float4 v = *(const float4*)(rsrc + (size_t)r * HD + k4);
        float hx = f_tf32(v.x), hy = f_tf32(v.y), hz = f_tf32(v.z), hw = f_tf32(v.w);
        sBh[r * GA_LD + k4 + 0] = hx; sBl[r * GA_LD + k4 + 0] = f_tf32(v.x - hx);
        sBh[r * GA_LD + k4 + 1] = hy; sBl[r * GA_LD + k4 + 1] = f_tf32(v.y - hy);
        sBh[r * GA_LD + k4 + 2] = hz; sBl[r * GA_LD + k4 + 2] = f_tf32(v.z - hz);
        sBh[r * GA_LD + k4 + 3] = hw; sBl[r * GA_LD + k4 + 3] = f_tf32(v.w - hw);
    }
    __syncthreads();

    const int warp = tid >> 5, lane = tid & 31;
    const int wr = warp & 1, wc = warp >> 1;       // 2 x 4 warp grid
    const int g = lane >> 2, tg = lane & 3;

    float d[2][4][4] = {};                          // [mtile][ntile][4]

    #pragma unroll
    for (int k0 = 0; k0 < HD; k0 += 8) {
        uint32_t ah[2][4], al[2][4], bhf[4][2], blf[4][2];
        #pragma unroll
        for (int mt = 0; mt < 2; mt++) {
            int r0 = wr * 32 + mt * 16 + g;
            ah[mt][0] = __float_as_uint(sAh[r0 * GA_LD + k0 + tg]);
            ah[mt][1] = __float_as_uint(sAh[(r0 + 8) * GA_LD + k0 + tg]);
            ah[mt][2] = __float_as_uint(sAh[r0 * GA_LD + k0 + tg + 4]);
            ah[mt][3] = __float_as_uint(sAh[(r0 + 8) * GA_LD + k0 + tg + 4]);
            al[mt][0] = __float_as_uint(sAl[r0 * GA_LD + k0 + tg]);
            al[mt][1] = __float_as_uint(sAl[(r0 + 8) * GA_LD + k0 + tg]);
            al[mt][2] = __float_as_uint(sAl[r0 * GA_LD + k0 + tg + 4]);
            al[mt][3] = __float_as_uint(sAl[(r0 + 8) * GA_LD + k0 + tg + 4]);
        }
        #pragma unroll
        for (int nt = 0; nt < 4; nt++) {
            int n0 = wc * 32 + nt * 8 + g;
            bhf[nt][0] = __float_as_uint(sBh[n0 * GA_LD + k0 + tg]);
            bhf[nt][1] = __float_as_uint(sBh[n0 * GA_LD + k0 + tg + 4]);
            blf[nt][0] = __float_as_uint(sBl[n0 * GA_LD + k0 + tg]);
            blf[nt][1] = __float_as_uint(sBl[n0 * GA_LD + k0 + tg + 4]);
        }
        #pragma unroll
        for (int mt = 0; mt < 2; mt++)
            #pragma unroll
            for (int nt = 0; nt < 4; nt++) {
                MMA_TF32(d[mt][nt], ah[mt], bhf[nt]);
                MMA_TF32(d[mt][nt], ah[mt], blf[nt]);
                MMA_TF32(d[mt][nt], al[mt], bhf[nt]);
            }
    }

    // store D tiles
    float* outp = g_score_all + ((size_t)bh * SL + it0) * NP + pt0;
    #pragma unroll
    for (int mt = 0; mt < 2; mt++) {
        int r0 = wr * 32 + mt * 16 + g;
        #pragma unroll
        for (int nt = 0; nt < 4; nt++) {
            int c0 = wc * 32 + nt * 8 + tg * 2;
            *(float2*)&outp[(size_t)r0 * NP + c0]       = make_float2(d[mt][nt][0], d[mt][nt][1]);
            *(float2*)&outp[(size_t)(r0 + 8) * NP + c0] = make_float2(d[mt][nt][2], d[mt][nt][3]);
        }
    }
}

// ===========================================================================
// Fused kernel: S = Q@K^T + gather(g_score_all), softmax, p write,
//               scatter -> SV (SMEM), attn = P@V + SV@RV
// ===========================================================================
__global__ void __launch_bounds__(NT, 1)
rel_attn_kernel(const float* __restrict__ Q, const float* __restrict__ K,
                const float* __restrict__ V, const float* __restrict__ RV,
                const int* __restrict__ PM32, const int* __restrict__ MSK,
                float* __restrict__ out_attn, float* __restrict__ out_p)
{
    extern __shared__ float sm[];
    float* sQ   = sm + SQ_OFF;   // [TI][68]
    float* sSA  = sm + SA_OFF;   // [TI][1028] : SV scatter buffer
    float* sBuf = sm + BUF_OFF;  // [256][68]; head reused as psum[4][16][68]
    float* sS   = sm + SS_OFF;   // [TI][516]

    const int b = blockIdx.z, h = blockIdx.y;
    const int i0 = blockIdx.x * TI;
    const int tid = threadIdx.x;
    const int pmshift = g_pm_is64;

    const size_t bh = (size_t)b * NH + h;
    const size_t qbase  = (bh * SL + i0) * HD;
    const size_t kvbase = bh * SL * HD;
    const size_t rbase  = bh * NP * HD;

    // ---- stage Q tile (float4) ----
    {
        const float4* src = (const float4*)(Q + qbase);
        for (int t = tid; t < TI * (HD / 4); t += NT) {
            int r = t >> 4, k4 = t & 15;
            *(float4*)&sQ[r * SQ_STRIDE + k4 * 4] = src[r * 16 + k4];
        }
    }
    __syncthreads();

    // dot-phase mapping over [16 x 256] chunk tile: 4 rows x 2 cols per thread
    const int dc0  = tid & 127;
    const int dc1  = dc0 + 128;
    const int drow = (tid >> 7) * 4;

    // ==== S[16][512] = Qtile @ K^T + gather(score_all), scale, mask ====
    const float inv = 0.125f;
    for (int j0 = 0; j0 < SL; j0 += CHUNK) {
        const float4* src = (const float4*)(K + kvbase + (size_t)j0 * HD);
        for (int t = tid; t < CHUNK * (HD / 4); t += NT) {
            int j = t >> 4, k4 = t & 15;
            *(float4*)&sBuf[j * BUF_STRIDE + k4 * 4] = src[j * 16 + k4];
        }
        __syncthreads();
        float acc[4][2] = {};
        #pragma unroll
        for (int k = 0; k < HD; k += 4) {
            float4 w0 = *(const float4*)&sBuf[dc0 * BUF_STRIDE + k];
            float4 w1 = *(const float4*)&sBuf[dc1 * BUF_STRIDE + k];
            #pragma unroll
            for (int r = 0; r < 4; r++) {
                float4 q = *(const float4*)&sQ[(drow + r) * SQ_STRIDE + k];
                acc[r][0] += q.x*w0.x + q.y*w0.y + q.z*w0.z + q.w*w0.w;
                acc[r][1] += q.x*w1.x + q.y*w1.y + q.z*w1.z + q.w*w1.w;
            }
        }
        #pragma unroll
        for (int r = 0; r < 4; r++) {
            int row = drow + r;
            size_t prow = ((size_t)b * SL + i0 + row) * SL;
            const int* mrow = MSK + (size_t)b * SL * SL + (size_t)(i0 + row) * SL;
            const float* srow = g_score_all + (bh * SL + (size_t)(i0 + row)) * NP;
            #pragma unroll
            for (int c = 0; c < 2; c++) {
                int col = j0 + (c ? dc1 : dc0);
                int idx = PM32[(prow + col) << pmshift];
                float sa = 0.f;
                if ((unsigned)idx < NP) sa = srow[idx];
                float s = (acc[r][c] + sa) * inv;
                if (mrow[col] == 0) s = -1e9f;
                sS[row * SS_STRIDE + col] = s;
            }
        }
        __syncthreads();
    }

    // ==== softmax: one warp per row + write p_attn ====
    {
        const int wid = tid >> 5, lane = tid & 31;
        const int r = wid;
        float m = -1e30f;
        for (int j = lane; j < SL; j += 32) m = fmaxf(m, sS[r * SS_STRIDE + j]);
        #pragma unroll
        for (int o = 16; o; o >>= 1) m = fmaxf(m, __shfl_xor_sync(0xffffffffu, m, o));
        float sum = 0.f;
        for (int j = lane; j < SL; j += 32) {
            float e = __expf(sS[r * SS_STRIDE + j] - m);
            sS[r * SS_STRIDE + j] = e;
            sum += e;
        }
        #pragma unroll
        for (int o = 16; o; o >>= 1) sum += __shfl_xor_sync(0xffffffffu, sum, o);
        float rs = 1.f / sum;
        size_t pbase = (bh * SL + (size_t)(i0 + r)) * SL;
        for (int j = lane; j < SL; j += 32) {
            float pv = sS[r * SS_STRIDE + j] * rs;
            sS[r * SS_STRIDE + j] = pv;
            if (out_p) out_p[pbase + j] = pv;
        }
    }
    __syncthreads();

    // ==== scatter p_attn into SV (sSA) ====
    for (int t = tid; t < TI * SA_STRIDE; t += NT) sSA[t] = 0.f;
    __syncthreads();
    for (int t = tid; t < TI * SL; t += NT) {
        int r = t >> 9, j = t & (SL - 1);
        size_t pmoff = ((size_t)b * SL + i0 + r) * SL + j;
        int idx = PM32[pmoff << pmshift];
        idx = min(max(idx, 0), NP);
        atomicAdd(&sSA[r * SA_STRIDE + idx], sS[r * SS_STRIDE + j]);
    }
    __syncthreads();

    // ==== output: attn = P@V + SV@RV ====
    const int ocg = (tid & 15) * 4;
    const int orp = ((tid >> 4) & 7) * 2;
    const int ojs = tid >> 7;
    float o00=0.f,o01=0.f,o02=0.f,o03=0.f;
    float o10=0.f,o11=0.f,o12=0.f,o13=0.f;

    // Part A: P @ V
    for (int j0 = 0; j0 < SL; j0 += CHUNK) {
        const float4* src = (const float4*)(V + kvbase + (size_t)j0 * HD);
        for (int t = tid; t < CHUNK * (HD / 4); t += NT) {
            int j = t >> 4, k4 = t & 15;
            *(float4*)&sBuf[j * BUF_STRIDE + k4 * 4] = src[j * 16 + k4];
        }
        __syncthreads();
        const int jlo = ojs * 64, jhi = jlo + 64;
        #pragma unroll 4
        for (int j = jlo; j < jhi; j += 4) {
            float4 p0 = *(const float4*)&sS[(orp + 0) * SS_STRIDE + j0 + j];
            float4 p1 = *(const float4*)&sS[(orp + 1) * SS_STRIDE + j0 + j];
            float4 v0 = *(const float4*)&sBuf[(j + 0) * BUF_STRIDE + ocg];
            float4 v1 = *(const float4*)&sBuf[(j + 1) * BUF_STRIDE + ocg];
            float4 v2 = *(const float4*)&sBuf[(j + 2) * BUF_STRIDE + ocg];
            float4 v3 = *(const float4*)&sBuf[(j + 3) * BUF_STRIDE + ocg];
            o00 += p0.x*v0.x + p0.y*v1.x + p0.z*v2.x + p0.w*v3.x;
            o01 += p0.x*v0.y + p0.y*v1.y + p0.z*v2.y + p0.w*v3.y;
            o02 += p0.x*v0.z + p0.y*v1.z + p0.z*v2.z + p0.w*v3.z;
            o03 += p0.x*v0.w + p0.y*v1.w + p0.z*v2.w + p0.w*v3.w;
            o10 += p1.x*v0.x + p1.y*v1.x + p1.z*v2.x + p1.w*v3.x;
            o11 += p1.x*v0.y + p1.y*v1.y + p1.z*v2.y + p1.w*v3.y;
            o12 += p1.x*v0.z + p1.y*v1.z + p1.z*v2.z + p1.w*v3.z;
            o13 += p1.x*v0.w + p1.y*v1.w + p1.z*v2.w + p1.w*v3.w;
        }
        __syncthreads();
    }

    // Part B: SV @ RV
    for (int p0 = 0; p0 < NP; p0 += CHUNK) {
        const float4* src = (const float4*)(RV + rbase + (size_t)p0 * HD);
        for (int t = tid; t < CHUNK * (HD / 4); t += NT) {
            int p = t >> 4, k4 = t & 15;
            *(float4*)&sBuf[p * BUF_STRIDE + k4 * 4] = src[p * 16 + k4];
        }
        __syncthreads();
        const int jlo = ojs * 64, jhi = jlo + 64;
        #pragma unroll 4
        for (int p = jlo; p < jhi; p += 4) {
            float4 a0 = *(const float4*)&sSA[(orp + 0) * SA_STRIDE + p0 + p];
            float4 a1 = *(const float4*)&sSA[(orp + 1) * SA_STRIDE + p0 + p];
            float4 v0 = *(const float4*)&sBuf[(p + 0) * BUF_STRIDE + ocg];
            float4 v1 = *(const float4*)&sBuf[(p + 1) * BUF_STRIDE + ocg];
            float4 v2 = *(const float4*)&sBuf[(p + 2) * BUF_STRIDE + ocg];
            float4 v3 = *(const float4*)&sBuf[(p + 3) * BUF_STRIDE + ocg];
            o00 += a0.x*v0.x + a0.y*v1.x + a0.z*v2.x + a0.w*v3.x;
            o01 += a0.x*v0.y + a0.y*v1.y + a0.z*v2.y + a0.w*v3.y;
            o02 += a0.x*v0.z + a0.y*v1.z + a0.z*v2.z + a0.w*v3.z;
            o03 += a0.x*v0.w + a0.y*v1.w + a0.z*v2.w + a0.w*v3.w;
            o10 += a1.x*v0.x + a1.y*v1.x + a1.z*v2.x + a1.w*v3.x;
            o11 += a1.x*v0.y + a1.y*v1.y + a1.z*v2.y + a1.w*v3.y;
            o12 += a1.x*v0.z + a1.y*v1.z + a1.z*v2.z + a1.w*v3.z;
            o13 += a1.x*v0.w + a1.y*v1.w + a1.z*v2.w + a1.w*v3.w;
        }
        __syncthreads();
    }

    // ---- reduce the 4 j-split partials via psum overlay in sBuf ----
    {
        float* psum = sBuf;
        float* base0 = psum + (ojs * TI + orp) * 68 + ocg;
        *(float4*)&base0[0]  = make_float4(o00, o01, o02, o03);
        *(float4*)&base0[68] = make_float4(o10, o11, o12, o13);
        __syncthreads();
        const size_t obase = (bh * SL + i0) * HD;
        for (int e = tid; e < TI * HD; e += NT) {
            int r = e >> 6, c = e & 63;
            float s = psum[(0 * TI + r) * 68 + c]
                    + psum[(1 * TI + r) * 68 + c]
                    + psum[(2 * TI + r) * 68 + c]
                    + psum[(3 * TI + r) * 68 + c];
            out_attn[obase + (size_t)r * HD + c] = s;
        }
    }
}

extern "C" void kernel_launch(void* const* d_in, const int* in_sizes, int n_in,
                              void* d_out, int out_size)
{
    int i4 = -1;
    for (int i = 0; i < n_in; i++) {
        if ((size_t)in_sizes[i] == R_ELEMS) { i4 = i; break; }
    }

    const float *Q, *K, *V, *RK, *RV;
    const int* PM32;
    const int* MSK;

    if (i4 == 4) {
        K    = (const float*)d_in[0];
        MSK  = (const int*)d_in[1];
        PM32 = (const int*)d_in[2];
        Q    = (const float*)d_in[3];
        RK   = (const float*)d_in[4];
        RV   = (const float*)d_in[5];
        V    = (const float*)d_in[6];
    } else {
        Q    = (const float*)d_in[0];
        K    = (const float*)d_in[1];
        V    = (const float*)d_in[2];
        RK   = (const float*)d_in[3];
        RV   = (const float*)d_in[4];
        PM32 = (const int*)d_in[5];
        MSK  = (const int*)d_in[6];
    }

    float* out = (float*)d_out;
    float* out_attn;
    float* out_p;
    if ((size_t)out_size >= ATTN_ELEMS + P_ELEMS) {
        out_attn = out;
        out_p = out + ATTN_ELEMS;
    } else if ((size_t)out_size == ATTN_ELEMS) {
        out_attn = out;
        out_p = nullptr;
    } else {
        cudaGetSymbolAddress((void**)&out_attn, g_attn_scratch);
        out_p = out;
    }

    cudaFuncSetAttribute(rel_attn_kernel,
                         cudaFuncAttributeMaxDynamicSharedMemorySize, SMEM_BYTES);
    cudaFuncSetAttribute(score_all_kernel,
                         cudaFuncAttributeMaxDynamicSharedMemorySize, GA_SMEM_BYTES);

    detect_pm_kernel<<<1, 256>>>(PM32);

    // Kernel A: score_all = Q @ RK^T (tf32 tensor, 3x compensated)
    {
        dim3 ga_grid(NP / GA_PT, SL / GA_IT, BS * NH);
        score_all_kernel<<<ga_grid, 256, GA_SMEM_BYTES>>>(Q, RK);
    }

    // Fused kernel
    dim3 grid(SL / TI, NH, BS);
    rel_attn_kernel<<<grid, NT, SMEM_BYTES>>>(Q, K, V, RV, PM32, MSK, out_attn, out_p);
}

// round 16
// speedup vs baseline: 3.4243x; 1.2675x over previous
#include <cuda_runtime.h>
#include <cstdint>

// Problem shapes (fixed for this instance)
#define BS 8
#define NH 8
#define SL 512
#define HD 64
#define NP 1024

#define TI 16     // query rows per CTA (fused kernel)
#define NT 512    // threads per CTA (16 warps)
#define CHUNK 256 // staging chunk (rows of K)

// SMEM layout (floats); strides multiple of 4 for float4; stride%32=4 -> conflict-free
#define SQ_STRIDE 68
#define SA_STRIDE 1028
#define BUF_STRIDE 68
#define SS_STRIDE 516

#define SQ_OFF 0
#define SA_OFF (TI * SQ_STRIDE)                    // 1088
#define BUF_OFF (SA_OFF + TI * SA_STRIDE)          // 17536
#define SS_OFF (BUF_OFF + CHUNK * BUF_STRIDE)      // 34944
#define SMEM_FLOATS (SS_OFF + TI * SS_STRIDE)      // 43200
#define SMEM_BYTES (SMEM_FLOATS * 4)               // 172800 bytes

#define ATTN_ELEMS ((size_t)BS * NH * SL * HD)     // 2,097,152
#define P_ELEMS ((size_t)BS * NH * SL * SL)        // 16,777,216
#define R_ELEMS ((size_t)BS * NH * NP * HD)        // 4,194,304

__device__ float g_attn_scratch[ATTN_ELEMS];
__device__ int g_pm_is64;
// Precomputed relation scores: [bh][i][p], 134 MB
__device__ float g_score_all[(size_t)BS * NH * SL * NP];
// Scattered attention mass per path: [bh][i][p<1024], 128 MB
__device__ float g_scat[(size_t)BS * NH * SL * NP];
// Fallback p storage if harness doesn't want p_attn output
__device__ float g_p_fallback[P_ELEMS];

// Detect whether path_map buffer is int64 (odd int32 words all zero) or int32.
__global__ void detect_pm_kernel(const int* __restrict__ pm32)
{
    __shared__ int any_nonzero;
    if (threadIdx.x == 0) any_nonzero = 0;
    __syncthreads();
    for (int i = threadIdx.x; i < 4096; i += blockDim.x) {
        if (pm32[2 * i + 1] != 0) any_nonzero = 1;
    }
    __syncthreads();
    if (threadIdx.x == 0) g_pm_is64 = (any_nonzero == 0) ? 1 : 0;
}

__device__ __forceinline__ float f_tf32(float x) {
    uint32_t r;
    asm("cvt.rna.tf32.f32 %0, %1;" : "=r"(r) : "f"(x));
    return __uint_as_float(r);
}

#define MMA_TF32(d, a, b) \
    asm volatile("mma.sync.aligned.m16n8k8.row.col.f32.tf32.tf32.f32 " \
                 "{%0,%1,%2,%3},{%4,%5,%6,%7},{%8,%9},{%0,%1,%2,%3};" \
                 : "+f"((d)[0]), "+f"((d)[1]), "+f"((d)[2]), "+f"((d)[3]) \
                 : "r"((a)[0]), "r"((a)[1]), "r"((a)[2]), "r"((a)[3]), \
                   "r"((b)[0]), "r"((b)[1]))

// ===========================================================================
// Kernel A: g_score_all[bh][i][p] = sum_k Q[bh,i,k] * RK[bh,p,k]
// CTA tile 64(i) x 128(p), K=64 single stage, 8 warps (2m x 4n), 3xTF32.
// ===========================================================================
#define GA_IT 64
#define GA_PT 128
#define GA_LD 68
#define GA_SAH 0
#define GA_SAL (GA_IT * GA_LD)
#define GA_SBH (2 * GA_IT * GA_LD)
#define GA_SBL (2 * GA_IT * GA_LD + GA_PT * GA_LD)
#define GA_SMEM_BYTES ((2 * GA_IT * GA_LD + 2 * GA_PT * GA_LD) * 4)   // 104448

__global__ void __launch_bounds__(256, 1)
score_all_kernel(const float* __restrict__ Q, const float* __restrict__ RK)
{
    extern __shared__ float sg[];
    float* sAh = sg + GA_SAH;
    float* sAl = sg + GA_SAL;
    float* sBh = sg + GA_SBH;
    float* sBl = sg + GA_SBL;

    const int bh  = blockIdx.z;
    const int it0 = blockIdx.y * GA_IT;
    const int pt0 = blockIdx.x * GA_PT;
    const int tid = threadIdx.x;

    const float* qsrc = Q + ((size_t)bh * SL + it0) * HD;
    const float* rsrc = RK + ((size_t)bh * NP + pt0) * HD;

    for (int t = tid; t < GA_IT * (HD / 4); t += 256) {
        int r = t >> 4, k4 = (t & 15) * 4;
        float4 v = *(const float4*)(qsrc + (size_t)r * HD + k4);
        float hx = f_tf32(v.x), hy = f_tf32(v.y), hz = f_tf32(v.z), hw = f_tf32(v.w);
        sAh[r * GA_LD + k4 + 0] = hx; sAl[r * GA_LD + k4 + 0] = f_tf32(v.x - hx);
        sAh[r * GA_LD + k4 + 1] = hy; sAl[r * GA_LD + k4 + 1] = f_tf32(v.y - hy);
        sAh[r * GA_LD + k4 + 2] = hz; sAl[r * GA_LD + k4 + 2] = f_tf32(v.z - hz);
        sAh[r * GA_LD + k4 + 3] = hw; sAl[r * GA_LD + k4 + 3] = f_tf32(v.w - hw);
    }
    for (int t = tid; t < GA_PT * (HD / 4); t += 256) {
        int r = t >> 4, k4 = (t & 15) * 4;
        float4 v = *(const float4*)(rsrc + (size_t)r * HD + k4);
        float hx = f_tf32(v.x), hy = f_tf32(v.y), hz = f_tf32(v.z), hw = f_tf32(v.w);
        sBh[r * GA_LD + k4 + 0] = hx; sBl[r * GA_LD + k4 + 0] = f_tf32(v.x - hx);
        sBh[r * GA_LD + k4 + 1] = hy; sBl[r * GA_LD + k4 + 1] = f_tf32(v.y - hy);
        sBh[r * GA_LD + k4 + 2] = hz; sBl[r * GA_LD + k4 + 2] = f_tf32(v.z - hz);
        sBh[r * GA_LD + k4 + 3] = hw; sBl[r * GA_LD + k4 + 3] = f_tf32(v.w - hw);
    }
    __syncthreads();

    const int warp = tid >> 5, lane = tid & 31;
    const int wr = warp & 1, wc = warp >> 1;
    const int g = lane >> 2, tg = lane & 3;

    float d[2][4][4] = {};

    #pragma unroll
    for (int k0 = 0; k0 < HD; k0 += 8) {
        uint32_t ah[2][4], al[2][4], bhf[4][2], blf[4][2];
        #pragma unroll
        for (int mt = 0; mt < 2; mt++) {
            int r0 = wr * 32 + mt * 16 + g;
            ah[mt][0] = __float_as_uint(sAh[r0 * GA_LD + k0 + tg]);
            ah[mt][1] = __float_as_uint(sAh[(r0 + 8) * GA_LD + k0 + tg]);
            ah[mt][2] = __float_as_uint(sAh[r0 * GA_LD + k0 + tg + 4]);
            ah[mt][3] = __float_as_uint(sAh[(r0 + 8) * GA_LD + k0 + tg + 4]);
            al[mt][0] = __float_as_uint(sAl[r0 * GA_LD + k0 + tg]);
            al[mt][1] = __float_as_uint(sAl[(r0 + 8) * GA_LD + k0 + tg]);
            al[mt][2] = __float_as_uint(sAl[r0 * GA_LD + k0 + tg + 4]);
            al[mt][3] = __float_as_uint(sAl[(r0 + 8) * GA_LD + k0 + tg + 4]);
        }
        #pragma unroll
        for (int nt = 0; nt < 4; nt++) {
            int n0 = wc * 32 + nt * 8 + g;
            bhf[nt][0] = __float_as_uint(sBh[n0 * GA_LD + k0 + tg]);
            bhf[nt][1] = __float_as_uint(sBh[n0 * GA_LD + k0 + tg + 4]);
            blf[nt][0] = __float_as_uint(sBl[n0 * GA_LD + k0 + tg]);
            blf[nt][1] = __float_as_uint(sBl[n0 * GA_LD + k0 + tg + 4]);
        }
        #pragma unroll
        for (int mt = 0; mt < 2; mt++)
            #pragma unroll
            for (int nt = 0; nt < 4; nt++) {
                MMA_TF32(d[mt][nt], ah[mt], bhf[nt]);
                MMA_TF32(d[mt][nt], ah[mt], blf[nt]);
                MMA_TF32(d[mt][nt], al[mt], bhf[nt]);
            }
    }

    float* outp = g_score_all + ((size_t)bh * SL + it0) * NP + pt0;
    #pragma unroll
    for (int mt = 0; mt < 2; mt++) {
        int r0 = wr * 32 + mt * 16 + g;
        #pragma unroll
        for (int nt = 0; nt < 4; nt++) {
            int c0 = wc * 32 + nt * 8 + tg * 2;
            *(float2*)&outp[(size_t)r0 * NP + c0]       = make_float2(d[mt][nt][0], d[mt][nt][1]);
            *(float2*)&outp[(size_t)(r0 + 8) * NP + c0] = make_float2(d[mt][nt][2], d[mt][nt][3]);
        }
    }
}

// ===========================================================================
// Fused kernel: S = Q@K^T + gather(g_score_all), softmax, p write,
//               scatter -> scat (SMEM) -> dump to g_scat
// ===========================================================================
__global__ void __launch_bounds__(NT, 1)
rel_attn_kernel(const float* __restrict__ Q, const float* __restrict__ K,
                const int* __restrict__ PM32, const int* __restrict__ MSK,
                float* __restrict__ out_p)
{
    extern __shared__ float sm[];
    float* sQ   = sm + SQ_OFF;   // [TI][68]
    float* sSA  = sm + SA_OFF;   // [TI][1028] : scatter buffer (col NP dropped at dump)
    float* sBuf = sm + BUF_OFF;  // [256][68]
    float* sS   = sm + SS_OFF;   // [TI][516]

    const int b = blockIdx.z, h = blockIdx.y;
    const int i0 = blockIdx.x * TI;
    const int tid = threadIdx.x;
    const int pmshift = g_pm_is64;

    const size_t bh = (size_t)b * NH + h;
    const size_t qbase  = (bh * SL + i0) * HD;
    const size_t kvbase = bh * SL * HD;

    // ---- stage Q tile ----
    {
        const float4* src = (const float4*)(Q + qbase);
        for (int t = tid; t < TI * (HD / 4); t += NT) {
            int r = t >> 4, k4 = t & 15;
            *(float4*)&sQ[r * SQ_STRIDE + k4 * 4] = src[r * 16 + k4];
        }
    }
    __syncthreads();

    const int dc0  = tid & 127;
    const int dc1  = dc0 + 128;
    const int drow = (tid >> 7) * 4;

    // ==== S = Q@K^T + gather(score_all), scale, mask ====
    const float inv = 0.125f;
    for (int j0 = 0; j0 < SL; j0 += CHUNK) {
        const float4* src = (const float4*)(K + kvbase + (size_t)j0 * HD);
        for (int t = tid; t < CHUNK * (HD / 4); t += NT) {
            int j = t >> 4, k4 = t & 15;
            *(float4*)&sBuf[j * BUF_STRIDE + k4 * 4] = src[j * 16 + k4];
        }
        __syncthreads();
        float acc[4][2] = {};
        #pragma unroll
        for (int k = 0; k < HD; k += 4) {
            float4 w0 = *(const float4*)&sBuf[dc0 * BUF_STRIDE + k];
            float4 w1 = *(const float4*)&sBuf[dc1 * BUF_STRIDE + k];
            #pragma unroll
            for (int r = 0; r < 4; r++) {
                float4 q = *(const float4*)&sQ[(drow + r) * SQ_STRIDE + k];
                acc[r][0] += q.x*w0.x + q.y*w0.y + q.z*w0.z + q.w*w0.w;
                acc[r][1] += q.x*w1.x + q.y*w1.y + q.z*w1.z + q.w*w1.w;
            }
        }
        #pragma unroll
        for (int r = 0; r < 4; r++) {
            int row = drow + r;
            size_t prow = ((size_t)b * SL + i0 + row) * SL;
            const int* mrow = MSK + (size_t)b * SL * SL + (size_t)(i0 + row) * SL;
            const float* srow = g_score_all + (bh * SL + (size_t)(i0 + row)) * NP;
            #pragma unroll
            for (int c = 0; c < 2; c++) {
                int col = j0 + (c ? dc1 : dc0);
                int idx = PM32[(prow + col) << pmshift];
                float sa = 0.f;
                if ((unsigned)idx < NP) sa = srow[idx];
                float s = (acc[r][c] + sa) * inv;
                if (mrow[col] == 0) s = -1e9f;
                sS[row * SS_STRIDE + col] = s;
            }
        }
        __syncthreads();
    }

    // ==== softmax: one warp per row + write p ====
    {
        const int wid = tid >> 5, lane = tid & 31;
        const int r = wid;
        float m = -1e30f;
        for (int j = lane; j < SL; j += 32) m = fmaxf(m, sS[r * SS_STRIDE + j]);
        #pragma unroll
        for (int o = 16; o; o >>= 1) m = fmaxf(m, __shfl_xor_sync(0xffffffffu, m, o));
        float sum = 0.f;
        for (int j = lane; j < SL; j += 32) {
            float e = __expf(sS[r * SS_STRIDE + j] - m);
            sS[r * SS_STRIDE + j] = e;
            sum += e;
        }
        #pragma unroll
        for (int o = 16; o; o >>= 1) sum += __shfl_xor_sync(0xffffffffu, sum, o);
        float rs = 1.f / sum;
        size_t pbase = (bh * SL + (size_t)(i0 + r)) * SL;
        for (int j = lane; j < SL; j += 32) {
            float pv = sS[r * SS_STRIDE + j] * rs;
            sS[r * SS_STRIDE + j] = pv;
            out_p[pbase + j] = pv;
        }
    }
    __syncthreads();

    // ==== scatter p into sSA, then dump cols 0..1023 to g_scat ====
    for (int t = tid; t < TI * SA_STRIDE; t += NT) sSA[t] = 0.f;
    __syncthreads();
    for (int t = tid; t < TI * SL; t += NT) {
        int r = t >> 9, j = t & (SL - 1);
        size_t pmoff = ((size_t)b * SL + i0 + r) * SL + j;
        int idx = PM32[pmoff << pmshift];
        idx = min(max(idx, 0), NP);
        atomicAdd(&sSA[r * SA_STRIDE + idx], sS[r * SS_STRIDE + j]);
    }
    __syncthreads();
    {
        float* dst = g_scat + (bh * SL + (size_t)i0) * NP;
        for (int t = tid; t < TI * (NP / 4); t += NT) {
            int r = t >> 8, c4 = (t & 255) * 4;
            *(float4*)&dst[(size_t)r * NP + c4] = *(const float4*)&sSA[r * SA_STRIDE + c4];
        }
    }
}

// ===========================================================================
// Kernel C: attn[bh, m, n] = sum_j P[bh,m,j] V[bh,j,n] + sum_p scat[bh,m,p] RV[bh,p,n]
// CTA tile 128(m) x 64(n); K chunks of 64 (8 from P@V, 16 from scat@RV).
// 8 warps (4m x 2n), warp tile 32x32, 3xTF32.
// ===========================================================================
#define OC_MT 128
#define OC_LD 68
#define OC_SAH 0
#define OC_SAL (OC_MT * OC_LD)
#define OC_SBH (2 * OC_MT * OC_LD)
#define OC_SBL (2 * OC_MT * OC_LD + 64 * OC_LD)
#define OC_SMEM_BYTES ((2 * OC_MT * OC_LD + 2 * 64 * OC_LD) * 4)   // 104448

__global__ void __launch_bounds__(256, 1)
attn_out_kernel(const float* __restrict__ V, const float* __restrict__ RV,
                const float* __restrict__ P, float* __restrict__ out_attn)
{
    extern __shared__ float so[];
    float* sAh = so + OC_SAH;  // [128][68]
    float* sAl = so + OC_SAL;
    float* sBh = so + OC_SBH;  // [64][68] : B[k][n]
    float* sBl = so + OC_SBL;

    const int bh = blockIdx.y;
    const int m0 = blockIdx.x * OC_MT;
    const int tid = threadIdx.x;

    const int warp = tid >> 5, lane = tid & 31;
    const int wr = warp & 3, wc = warp >> 2;   // 4 m-warps x 2 n-warps
    const int g = lane >> 2, tg = lane & 3;

    float d[2][4][4] = {};

    for (int kc = 0; kc < 24; kc++) {
        const float* asrc;
        const float* bsrc;
        int alda;
        if (kc < 8) {
            int k0 = kc * 64;
            asrc = P + ((size_t)bh * SL + m0) * SL + k0;
            alda = SL;
            bsrc = V + (size_t)bh * SL * HD + (size_t)k0 * HD;
        } else {
            int k0 = (kc - 8) * 64;
            asrc = g_scat + ((size_t)bh * SL + m0) * NP + k0;
            alda = NP;
            bsrc = RV + (size_t)bh * NP * HD + (size_t)k0 * HD;
        }
        // stage A 128x64
        for (int t = tid; t < OC_MT * 16; t += 256) {
            int r = t >> 4, c4 = (t & 15) * 4;
            float4 v = *(const float4*)(asrc + (size_t)r * alda + c4);
            float hx = f_tf32(v.x), hy = f_tf32(v.y), hz = f_tf32(v.z), hw = f_tf32(v.w);
            sAh[r * OC_LD + c4 + 0] = hx; sAl[r * OC_LD + c4 + 0] = f_tf32(v.x - hx);
            sAh[r * OC_LD + c4 + 1] = hy; sAl[r * OC_LD + c4 + 1] = f_tf32(v.y - hy);
            sAh[r * OC_LD + c4 + 2] = hz; sAl[r * OC_LD + c4 + 2] = f_tf32(v.z - hz);
            sAh[r * OC_LD + c4 + 3] = hw; sAl[r * OC_LD + c4 + 3] = f_tf32(v.w - hw);
        }
        // stage B 64x64 (rows k, cols n)
        for (int t = tid; t < 64 * 16; t += 256) {
            int r = t >> 4, c4 = (t & 15) * 4;
            float4 v = *(const float4*)(bsrc + (size_t)r * HD + c4);
            float hx = f_tf32(v.x), hy = f_tf32(v.y), hz = f_tf32(v.z), hw = f_tf32(v.w);
            sBh[r * OC_LD + c4 + 0] = hx; sBl[r * OC_LD + c4 + 0] = f_tf32(v.x - hx);
            sBh[r * OC_LD + c4 + 1] = hy; sBl[r * OC_LD + c4 + 1] = f_tf32(v.y - hy);
            sBh[r * OC_LD + c4 + 2] = hz; sBl[r * OC_LD + c4 + 2] = f_tf32(v.z - hz);
            sBh[r * OC_LD + c4 + 3] = hw; sBl[r * OC_LD + c4 + 3] = f_tf32(v.w - hw);
        }
        __syncthreads();

        #pragma unroll
        for (int kk = 0; kk < 64; kk += 8) {
            uint32_t ah[2][4], al[2][4], bhf[4][2], blf[4][2];
            #pragma unroll
            for (int mt = 0; mt < 2; mt++) {
                int r0 = wr * 32 + mt * 16 + g;
                ah[mt][0] = __float_as_uint(sAh[r0 * OC_LD + kk + tg]);
                ah[mt][1] = __float_as_uint(sAh[(r0 + 8) * OC_LD + kk + tg]);
                ah[mt][2] = __float_as_uint(sAh[r0 * OC_LD + kk + tg + 4]);
                ah[mt][3] = __float_as_uint(sAh[(r0 + 8) * OC_LD + kk + tg + 4]);
                al[mt][0] = __float_as_uint(sAl[r0 * OC_LD + kk + tg]);
                al[mt][1] = __float_as_uint(sAl[(r0 + 8) * OC_LD + kk + tg]);
                al[mt][2] = __float_as_uint(sAl[r0 * OC_LD + kk + tg + 4]);
                al[mt][3] = __float_as_uint(sAl[(r0 + 8) * OC_LD + kk + tg + 4]);
            }
            #pragma unroll
            for (int nt = 0; nt < 4; nt++) {
                int n0 = wc * 32 + nt * 8 + g;
                bhf[nt][0] = __float_as_uint(sBh[(kk + tg) * OC_LD + n0]);
                bhf[nt][1] = __float_as_uint(sBh[(kk + tg + 4) * OC_LD + n0]);
                blf[nt][0] = __float_as_uint(sBl[(kk + tg) * OC_LD + n0]);
                blf[nt][1] = __float_as_uint(sBl[(kk + tg + 4) * OC_LD + n0]);
            }
            #pragma unroll
            for (int mt = 0; mt < 2; mt++)
                #pragma unroll
                for (int nt = 0; nt < 4; nt++) {
                    MMA_TF32(d[mt][nt], ah[mt], bhf[nt]);
                    MMA_TF32(d[mt][nt], ah[mt], blf[nt]);
                    MMA_TF32(d[mt][nt], al[mt], bhf[nt]);
                }
        }
        __syncthreads();
    }

    float* outp = out_attn + ((size_t)bh * SL + m0) * HD;
    #pragma unroll
    for (int mt = 0; mt < 2; mt++) {
        int r0 = wr * 32 + mt * 16 + g;
        #pragma unroll
        for (int nt = 0; nt < 4; nt++) {
            int c0 = wc * 32 + nt * 8 + tg * 2;
            *(float2*)&outp[(size_t)r0 * HD + c0]       = make_float2(d[mt][nt][0], d[mt][nt][1]);
            *(float2*)&outp[(size_t)(r0 + 8) * HD + c0] = make_float2(d[mt][nt][2], d[mt][nt][3]);
        }
    }
}

extern "C" void kernel_launch(void* const* d_in, const int* in_sizes, int n_in,
                              void* d_out, int out_size)
{
    int i4 = -1;
    for (int i = 0; i < n_in; i++) {
        if ((size_t)in_sizes[i] == R_ELEMS) { i4 = i; break; }
    }

    const float *Q, *K, *V, *RK, *RV;
    const int* PM32;
    const int* MSK;

    if (i4 == 4) {
        K    = (const float*)d_in[0];
        MSK  = (const int*)d_in[1];
        PM32 = (const int*)d_in[2];
        Q    = (const float*)d_in[3];
        RK   = (const float*)d_in[4];
        RV   = (const float*)d_in[5];
        V    = (const float*)d_in[6];
    } else {
        Q    = (const float*)d_in[0];
        K    = (const float*)d_in[1];
        V    = (const float*)d_in[2];
        RK   = (const float*)d_in[3];
        RV   = (const float*)d_in[4];
        PM32 = (const int*)d_in[5];
        MSK  = (const int*)d_in[6];
    }

    float* out = (float*)d_out;
    float* out_attn;
    float* out_p;
    if ((size_t)out_size >= ATTN_ELEMS + P_ELEMS) {
        out_attn = out;
        out_p = out + ATTN_ELEMS;
    } else if ((size_t)out_size == ATTN_ELEMS) {
        out_attn = out;
        out_p = nullptr;
    } else {
        cudaGetSymbolAddress((void**)&out_attn, g_attn_scratch);
        out_p = out;
    }
    float* p_store = out_p;
    if (!p_store) cudaGetSymbolAddress((void**)&p_store, g_p_fallback);

    cudaFuncSetAttribute(rel_attn_kernel,
                         cudaFuncAttributeMaxDynamicSharedMemorySize, SMEM_BYTES);
    cudaFuncSetAttribute(score_all_kernel,
                         cudaFuncAttributeMaxDynamicSharedMemorySize, GA_SMEM_BYTES);
    cudaFuncSetAttribute(attn_out_kernel,
                         cudaFuncAttributeMaxDynamicSharedMemorySize, OC_SMEM_BYTES);

    detect_pm_kernel<<<1, 256>>>(PM32);

    // Kernel A: score_all = Q @ RK^T
    {
        dim3 ga_grid(NP / GA_PT, SL / GA_IT, BS * NH);
        score_all_kernel<<<ga_grid, 256, GA_SMEM_BYTES>>>(Q, RK);
    }

    // Fused: scores, softmax, p write, scatter dump
    {
        dim3 grid(SL / TI, NH, BS);
        rel_attn_kernel<<<grid, NT, SMEM_BYTES>>>(Q, K, PM32, MSK, p_store);
    }

    // Kernel C: attn = P@V + scat@RV
    {
        dim3 oc_grid(SL / OC_MT, BS * NH);
        attn_out_kernel<<<oc_grid, 256, OC_SMEM_BYTES>>>(V, RV, p_store, out_attn);
    }
}